// round 9
// baseline (speedup 1.0000x reference)
#include <cuda_runtime.h>
#include <cuda_bf16.h>
#include <stdint.h>

#define BN 4096
#define DD 128
#define EPSF 1e-6f
#define NWORDS (BN/32)        // 128 mask words per row
#define PART 64               // 32 j-tiles * 2 warp-col-halves per row
#define TILE 128
#define LDKB 272              // padded smem row stride (136 bf16) -> conflict-free ldmatrix
#define TILEB (128 * LDKB)    // 34816 bytes per 128x128 bf16 tile

// ---------------- device scratch (static; no allocations allowed) ----------
__device__ float g_sq[BN];
__device__ float g_s[BN];
__device__ __nv_bfloat16 g_hi[BN * DD];
__device__ __nv_bfloat16 g_mid[BN * DD];
__device__ __nv_bfloat16 g_lo[BN * DD];
__device__ unsigned g_posbits[BN * NWORDS];
__device__ unsigned g_negbits[BN * NWORDS];
__device__ unsigned long long g_posPart[(size_t)BN * PART];
__device__ unsigned long long g_negPart[(size_t)BN * PART];
__device__ float g_loss[BN];
__device__ float g_w[BN];

// ---------------- smem layout (dynamic) -------------------------------------
#define SM_TILES 0                       // 6 tiles: A hi/mid/lo, B hi/mid/lo
#define SM_SQI   (6 * TILEB)             // 128 floats
#define SM_SI    (SM_SQI + 512)
#define SM_SQJ   (SM_SI + 512)
#define SM_SJ    (SM_SQJ + 512)
#define SM_POS   (SM_SJ + 512)           // 128 rows x 4 words
#define SM_NEG   (SM_POS + 2048)
#define SM_TOTAL (SM_NEG + 2048)         // 215040 bytes

// ---------------- helpers ----------------------------------------------------
__device__ __forceinline__ uint32_t smem_to_u32(const void* p) {
    uint32_t a;
    asm("{ .reg .u64 t; cvta.to.shared.u64 t, %1; cvt.u32.u64 %0, t; }" : "=r"(a) : "l"(p));
    return a;
}
__device__ __forceinline__ void ldsm_x4(uint32_t addr, uint32_t* r) {
    asm volatile("ldmatrix.sync.aligned.m8n8.x4.shared.b16 {%0,%1,%2,%3}, [%4];"
                 : "=r"(r[0]), "=r"(r[1]), "=r"(r[2]), "=r"(r[3]) : "r"(addr));
}
__device__ __forceinline__ void mma16816(float* c, const uint32_t* a,
                                         uint32_t b0, uint32_t b1) {
    asm volatile(
        "mma.sync.aligned.m16n8k16.row.col.f32.bf16.bf16.f32 "
        "{%0,%1,%2,%3}, {%4,%5,%6,%7}, {%8,%9}, {%0,%1,%2,%3};"
        : "+f"(c[0]), "+f"(c[1]), "+f"(c[2]), "+f"(c[3])
        : "r"(a[0]), "r"(a[1]), "r"(a[2]), "r"(a[3]), "r"(b0), "r"(b1));
}

// ---------------- kernel 1: row sums, bf16 3-split, packed masks -----------
__global__ void prep_kernel(const float* __restrict__ E,
                            const int* __restrict__ tgt,
                            const unsigned* __restrict__ P,
                            const unsigned* __restrict__ N)
{
    int i = blockIdx.x;
    int t = threadIdx.x;            // 128 threads

    float v = E[(size_t)i * DD + t];

    // 3-way bf16 split (residual ~2^-26 relative)
    __nv_bfloat16 bh = __float2bfloat16(v);
    float r1 = v - __bfloat162float(bh);
    __nv_bfloat16 bm = __float2bfloat16(r1);
    float r2 = r1 - __bfloat162float(bm);
    __nv_bfloat16 bl = __float2bfloat16(r2);
    g_hi [(size_t)i * DD + t] = bh;
    g_mid[(size_t)i * DD + t] = bm;
    g_lo [(size_t)i * DD + t] = bl;

    float s = v, q = v * v;
    #pragma unroll
    for (int o = 16; o; o >>= 1) {
        s += __shfl_down_sync(0xffffffffu, s, o);
        q += __shfl_down_sync(0xffffffffu, q, o);
    }
    __shared__ float ss[4], qq[4];
    if ((t & 31) == 0) { ss[t >> 5] = s; qq[t >> 5] = q; }
    __syncthreads();
    if (t == 0) {
        g_s[i]  = ss[0] + ss[1] + ss[2] + ss[3];
        g_sq[i] = qq[0] + qq[1] + qq[2] + qq[3];
    }

    // bit-pack permuted masks (32-bit bool elements; nonzero == true)
    const unsigned* Pi = P + (size_t)i * BN;
    const unsigned* Ni = N + (size_t)i * BN;
    unsigned pm = 0u, nm = 0u;
    int base = t * 32;
    #pragma unroll 8
    for (int u = 0; u < 32; u++) {
        int tj = tgt[base + u];
        pm |= (Pi[tj] != 0u ? 1u : 0u) << u;
        nm |= (Ni[tj] != 0u ? 1u : 0u) << u;
    }
    g_posbits[i * NWORDS + t] = pm;
    g_negbits[i * NWORDS + t] = nm;
}

// ---------------- kernel 2: mma.sync split-bf16 GEMM + argmax epilogue -----
// 128x128 tile, K=128, 8 warps (4x2), each warp 32x64, m16n8k16 bf16 HMMA.
__global__ __launch_bounds__(256, 1)
void main_kernel()
{
    extern __shared__ char smem[];
    const uint32_t sbase = smem_to_u32(smem);
    const int tid  = threadIdx.x;
    const int lane = tid & 31, warp = tid >> 5;
    const int wr = warp >> 1, wc = warp & 1;     // warp row/col in 4x2 grid
    const int g  = lane >> 2, tig = lane & 3;
    const int j0 = blockIdx.x * TILE;
    const int i0 = blockIdx.y * TILE;

    // ---- stage 6 bf16 tiles + row stats + masks ----
    const __nv_bfloat16* srcs[6] = { g_hi, g_mid, g_lo, g_hi, g_mid, g_lo };
    #pragma unroll
    for (int tile = 0; tile < 6; tile++) {
        const __nv_bfloat16* src = srcs[tile] + (size_t)(tile < 3 ? i0 : j0) * DD;
        char* dst = smem + SM_TILES + tile * TILEB;
        #pragma unroll
        for (int it = 0; it < 8; it++) {
            int m = tid + it * 256;              // 0..2047 16B chunks
            int row = m >> 4, ch = m & 15;
            uint4 v = *(const uint4*)(src + (size_t)row * DD + ch * 8);
            *(uint4*)(dst + row * LDKB + ch * 16) = v;
        }
    }
    if (tid < 128) {
        ((float*)(smem + SM_SQI))[tid] = g_sq[i0 + tid];
        ((float*)(smem + SM_SI ))[tid] = g_s [i0 + tid];
        ((float*)(smem + SM_SQJ))[tid] = g_sq[j0 + tid];
        ((float*)(smem + SM_SJ ))[tid] = g_s [j0 + tid];
    }
    {
        const int wbase = j0 >> 5;
        #pragma unroll
        for (int m = tid; m < 512; m += 256) {
            int r = m >> 2, w = m & 3;
            ((unsigned*)(smem + SM_POS))[m] = g_posbits[(i0 + r) * NWORDS + wbase + w];
            ((unsigned*)(smem + SM_NEG))[m] = g_negbits[(i0 + r) * NWORDS + wbase + w];
        }
    }
    __syncthreads();

    // ---- mainloop: 6 split terms x 8 k-steps x 16 mma ----
    float acc[2][8][4];
    #pragma unroll
    for (int mb = 0; mb < 2; mb++)
        #pragma unroll
        for (int nb = 0; nb < 8; nb++)
            #pragma unroll
            for (int c = 0; c < 4; c++) acc[mb][nb][c] = 0.0f;

    const int m0 = 32 * wr;
    const int n0 = 64 * wc;
    const uint32_t arow = (uint32_t)(m0 + (lane & 15));
    const uint32_t asel = (lane >> 4) << 3;            // 0 or 8 (k offset)
    const uint32_t bsel = ((lane >> 3) & 1) << 3;
    const uint32_t brow0 = (uint32_t)(((lane >> 4) << 3) + (lane & 7));

    #pragma unroll
    for (int tm = 0; tm < 6; tm++) {
        const int tA[6] = {0, 0, 1, 0, 2, 1};
        const int tB[6] = {0, 1, 0, 2, 0, 1};
        const uint32_t Ab = sbase + SM_TILES + tA[tm] * TILEB;
        const uint32_t Bb = sbase + SM_TILES + (3 + tB[tm]) * TILEB;
        #pragma unroll
        for (int k = 0; k < 8; k++) {
            const int kb = k * 16;
            uint32_t a0[4], a1[4], bfg[4][4];
            uint32_t aaddr = Ab + arow * LDKB + (kb + asel) * 2;
            ldsm_x4(aaddr, a0);
            ldsm_x4(aaddr + 16 * LDKB, a1);
            #pragma unroll
            for (int p = 0; p < 4; p++) {
                uint32_t baddr = Bb + (uint32_t)(n0 + p * 16 + brow0) * LDKB
                               + (kb + bsel) * 2;
                ldsm_x4(baddr, bfg[p]);
            }
            #pragma unroll
            for (int p = 0; p < 4; p++)
                #pragma unroll
                for (int s = 0; s < 2; s++) {
                    const int nb = 2 * p + s;
                    mma16816(acc[0][nb], a0, bfg[p][2 * s], bfg[p][2 * s + 1]);
                    mma16816(acc[1][nb], a1, bfg[p][2 * s], bfg[p][2 * s + 1]);
                }
        }
    }

    // ---- epilogue: distances + masked argmax/argmin, quad reduce ----
    const float* SQI = (const float*)(smem + SM_SQI);
    const float* SI  = (const float*)(smem + SM_SI);
    const float* SQJ = (const float*)(smem + SM_SQJ);
    const float* SJ  = (const float*)(smem + SM_SJ);
    const unsigned* POS = (const unsigned*)(smem + SM_POS);
    const unsigned* NEG = (const unsigned*)(smem + SM_NEG);
    const float deps = (float)DD * (EPSF * EPSF);

    #pragma unroll
    for (int mb = 0; mb < 2; mb++)
    #pragma unroll
    for (int rh = 0; rh < 2; rh++) {
        const int iloc = 32 * wr + 16 * mb + 8 * rh + g;
        const int i = i0 + iloc;
        const float sqi = SQI[iloc], si = SI[iloc];
        unsigned long long bp = 0ull;
        unsigned long long bn = 0xFFFFFFFFFFFFFFFFull;
        #pragma unroll
        for (int nb = 0; nb < 8; nb++) {
            #pragma unroll
            for (int e = 0; e < 2; e++) {
                const int jl = 64 * wc + 8 * nb + 2 * tig + e;
                const float S = acc[mb][nb][2 * rh + e];
                float d2 = sqi + SQJ[jl] - 2.0f * S
                         + 2.0f * EPSF * (si - SJ[jl]) + deps;
                float dmv = sqrtf(fmaxf(d2, 0.0f));
                unsigned bits = __float_as_uint(dmv);
                unsigned j = (unsigned)(j0 + jl);
                unsigned pw = POS[iloc * 4 + (jl >> 5)];
                unsigned nw = NEG[iloc * 4 + (jl >> 5)];
                if ((pw >> (jl & 31)) & 1u) {
                    unsigned long long pk = ((unsigned long long)bits << 32) | (~j);
                    if (pk > bp) bp = pk;       // ties: smaller j wins (~j larger)
                }
                if ((nw >> (jl & 31)) & 1u) {
                    unsigned long long pk = ((unsigned long long)bits << 32) | j;
                    if (pk < bn) bn = pk;       // ties: smaller j wins
                }
            }
        }
        #pragma unroll
        for (int o = 1; o <= 2; o <<= 1) {
            unsigned long long a = __shfl_xor_sync(0xffffffffu, bp, o); if (a > bp) bp = a;
            unsigned long long b = __shfl_xor_sync(0xffffffffu, bn, o); if (b < bn) bn = b;
        }
        if (tig == 0) {
            g_posPart[(size_t)i * PART + blockIdx.x * 2 + wc] = bp;
            g_negPart[(size_t)i * PART + blockIdx.x * 2 + wc] = bn;
        }
    }
}

// ---------------- kernel 3: per-row reduce + exact triplet loss ------------
__global__ void row_kernel(const float* __restrict__ E)
{
    int i = blockIdx.x;
    int t = threadIdx.x;            // 128 threads

    unsigned long long bp = 0ull, bn = 0xFFFFFFFFFFFFFFFFull;
    for (int p = t; p < PART; p += 128) {
        unsigned long long a = g_posPart[(size_t)i * PART + p]; if (a > bp) bp = a;
        unsigned long long b = g_negPart[(size_t)i * PART + p]; if (b < bn) bn = b;
    }
    #pragma unroll
    for (int o = 16; o; o >>= 1) {
        unsigned long long a = __shfl_down_sync(0xffffffffu, bp, o); if (a > bp) bp = a;
        unsigned long long b = __shfl_down_sync(0xffffffffu, bn, o); if (b < bn) bn = b;
    }
    __shared__ unsigned long long sp[4], sn[4], shP, shN;
    if ((t & 31) == 0) { sp[t >> 5] = bp; sn[t >> 5] = bn; }
    __syncthreads();
    if (t == 0) {
        bp = sp[0]; bn = sn[0];
        for (int w = 1; w < 4; w++) { if (sp[w] > bp) bp = sp[w]; if (sn[w] < bn) bn = sn[w]; }
        shP = bp; shN = bn;
    }
    __syncthreads();
    bp = shP; bn = shN;

    if (bp == 0ull || bn == 0xFFFFFFFFFFFFFFFFull) {   // invalid row
        if (t == 0) { g_loss[i] = 0.0f; g_w[i] = 0.0f; }
        return;
    }
    int pi = (int)(~(unsigned)bp) & (BN - 1);   // undo ~j
    int ni = (int)((unsigned)bn);

    float av = E[(size_t)i  * DD + t];
    float pv = E[(size_t)pi * DD + t];
    float nv = E[(size_t)ni * DD + t];
    float d1 = av - pv + EPSF;
    float d2 = av - nv + EPSF;
    float d3 = pv - nv + EPSF;
    float s1 = d1 * d1, s2 = d2 * d2, s3 = d3 * d3;
    #pragma unroll
    for (int o = 16; o; o >>= 1) {
        s1 += __shfl_down_sync(0xffffffffu, s1, o);
        s2 += __shfl_down_sync(0xffffffffu, s2, o);
        s3 += __shfl_down_sync(0xffffffffu, s3, o);
    }
    __shared__ float r1[4], r2[4], r3[4];
    if ((t & 31) == 0) { r1[t >> 5] = s1; r2[t >> 5] = s2; r3[t >> 5] = s3; }
    __syncthreads();
    if (t == 0) {
        float S1 = r1[0] + r1[1] + r1[2] + r1[3];
        float S2 = r2[0] + r2[1] + r2[2] + r2[3];
        float S3 = r3[0] + r3[1] + r3[2] + r3[3];
        float ap = sqrtf(S1), an = sqrtf(S2), pn = sqrtf(S3);
        float loss = fmaxf(ap - fminf(an, pn) + 1.0f, 0.0f);
        g_loss[i] = loss;
        g_w[i] = 1.0f;
    }
}

// ---------------- kernel 4: deterministic scalar reduction -----------------
__global__ void final_kernel(float* __restrict__ out)
{
    int t = threadIdx.x;            // 1024 threads
    float ls = 0.0f, ws = 0.0f;
    for (int r = t; r < BN; r += 1024) { ls += g_loss[r]; ws += g_w[r]; }
    #pragma unroll
    for (int o = 16; o; o >>= 1) {
        ls += __shfl_down_sync(0xffffffffu, ls, o);
        ws += __shfl_down_sync(0xffffffffu, ws, o);
    }
    __shared__ float sl[32], sw[32];
    if ((t & 31) == 0) { sl[t >> 5] = ls; sw[t >> 5] = ws; }
    __syncthreads();
    if (t == 0) {
        float L = 0.0f, W = 0.0f;
        for (int w = 0; w < 32; w++) { L += sl[w]; W += sw[w]; }
        out[0] = L / fmaxf(W, 1.0f);
    }
}

// ---------------- launch ----------------------------------------------------
extern "C" void kernel_launch(void* const* d_in, const int* in_sizes, int n_in,
                              void* d_out, int out_size)
{
    const float*    E   = (const float*)d_in[0];
    const int*      tgt = (const int*)d_in[1];
    const unsigned* P   = (const unsigned*)d_in[2];
    const unsigned* N   = (const unsigned*)d_in[3];
    float* out = (float*)d_out;

    cudaFuncSetAttribute(main_kernel, cudaFuncAttributeMaxDynamicSharedMemorySize, SM_TOTAL);

    prep_kernel<<<BN, 128>>>(E, tgt, P, N);
    dim3 grid(32, 32);
    main_kernel<<<grid, 256, SM_TOTAL>>>();
    row_kernel<<<BN, 128>>>(E);
    final_kernel<<<1, 1024>>>(out);
}

// round 12
// speedup vs baseline: 1.8506x; 1.8506x over previous
#include <cuda_runtime.h>
#include <stdint.h>

#define BN 4096
#define DD 128
#define EPSF 1e-6f
#define NWORDS (BN/32)        // 128 words per row
#define PART 512              // 32 "other-tile" slots * 16 lane slots per row
#define TK 32                 // K chunk
#define NT 32                 // 32 row/col tiles
#define NBLK 528              // NT*(NT+1)/2 upper-triangular blocks

// ---------------- device scratch (static; no allocations allowed) ----------
__device__ float g_sq[BN];
__device__ float g_s[BN];
__device__ unsigned g_posbits[BN * NWORDS];
__device__ unsigned g_negbits[BN * NWORDS];
__device__ unsigned long long g_posPart[(size_t)BN * PART];
__device__ unsigned long long g_negPart[(size_t)BN * PART];
__device__ float g_loss[BN];
__device__ float g_w[BN];

// ---------------- f32x2 helpers (sm_100+ base ISA) --------------------------
typedef unsigned long long ull;
__device__ __forceinline__ ull fma2(ull a, ull b, ull c) {
    ull d;
    asm("fma.rn.f32x2 %0, %1, %2, %3;" : "=l"(d) : "l"(a), "l"(b), "l"(c));
    return d;
}
__device__ __forceinline__ ull pack2(float lo, float hi) {
    ull d;
    asm("mov.b64 %0, {%1, %2};" : "=l"(d) : "f"(lo), "f"(hi));
    return d;
}
__device__ __forceinline__ void unpack2(ull v, float& lo, float& hi) {
    asm("mov.b64 {%0, %1}, %2;" : "=f"(lo), "=f"(hi) : "l"(v));
}

// ---------------- kernel 1: row sums + bit-packed permuted masks -----------
// Masks arrive as 4-byte bool elements; nonzero 32-bit word <=> true.
__global__ void prep_kernel(const float* __restrict__ E,
                            const int* __restrict__ tgt,
                            const unsigned* __restrict__ P,
                            const unsigned* __restrict__ N)
{
    int i = blockIdx.x;
    int t = threadIdx.x;            // 128 threads

    float v = E[(size_t)i * DD + t];
    float s = v, q = v * v;
    #pragma unroll
    for (int o = 16; o; o >>= 1) {
        s += __shfl_down_sync(0xffffffffu, s, o);
        q += __shfl_down_sync(0xffffffffu, q, o);
    }
    __shared__ float ss[4], qq[4];
    if ((t & 31) == 0) { ss[t >> 5] = s; qq[t >> 5] = q; }
    __syncthreads();
    if (t == 0) {
        g_s[i]  = ss[0] + ss[1] + ss[2] + ss[3];
        g_sq[i] = qq[0] + qq[1] + qq[2] + qq[3];
    }

    const unsigned* Pi = P + (size_t)i * BN;
    const unsigned* Ni = N + (size_t)i * BN;
    unsigned pm = 0u, nm = 0u;
    int base = t * 32;
    #pragma unroll 8
    for (int u = 0; u < 32; u++) {
        int tj = tgt[base + u];
        pm |= (Pi[tj] != 0u ? 1u : 0u) << u;
        nm |= (Ni[tj] != 0u ? 1u : 0u) << u;
    }
    g_posbits[i * NWORDS + t] = pm;
    g_negbits[i * NWORDS + t] = nm;
}

// ---------------- kernel 2: symmetric tiled SGEMM (f32x2) + dual epilogue --
__device__ __forceinline__ int tri_off(int k) { return k * 32 - (k * (k - 1)) / 2; }

__global__ __launch_bounds__(256, 2)
void main_kernel(const float* __restrict__ E)
{
    __shared__ float As[TK][132];   // [k][i]
    __shared__ float Bs[TK][132];   // [k][j]
    __shared__ float sSqI[128], sSI[128], sSqJ[128], sSJ[128];
    __shared__ unsigned smPos[128][4], smNeg[128][4];    // i-rows @ j-range
    __shared__ unsigned smPos2[128][4], smNeg2[128][4];  // j-rows @ i-range

    const int tid = threadIdx.x;
    const int tx = tid & 15;        // j direction
    const int ty = tid >> 4;        // i direction

    // triangular decode: block t -> (bi, bj), bi <= bj
    const int tblk = blockIdx.x;
    int bi = (int)floorf((65.0f - sqrtf(4225.0f - 8.0f * (float)tblk)) * 0.5f);
    if (bi < 0) bi = 0; if (bi > 31) bi = 31;
    while (tri_off(bi + 1) <= tblk) bi++;
    while (tri_off(bi) > tblk) bi--;
    const int bj = bi + (tblk - tri_off(bi));
    const int i0 = bi * 128;
    const int j0 = bj * 128;
    const bool diag = (bi == bj);

    if (tid < 128) {
        sSqI[tid] = g_sq[i0 + tid]; sSI[tid] = g_s[i0 + tid];
        sSqJ[tid] = g_sq[j0 + tid]; sSJ[tid] = g_s[j0 + tid];
    }
    for (int m = tid; m < 512; m += 256) {
        int r = m >> 2, w = m & 3;
        smPos [r][w] = g_posbits[(i0 + r) * NWORDS + (j0 >> 5) + w];
        smNeg [r][w] = g_negbits[(i0 + r) * NWORDS + (j0 >> 5) + w];
        smPos2[r][w] = g_posbits[(j0 + r) * NWORDS + (i0 >> 5) + w];
        smNeg2[r][w] = g_negbits[(j0 + r) * NWORDS + (i0 >> 5) + w];
    }

    ull acc2[8][4];                 // 8 i-rows x 4 j-pairs (f32x2)
    #pragma unroll
    for (int r = 0; r < 8; r++)
        #pragma unroll
        for (int c = 0; c < 4; c++) acc2[r][c] = 0ull;

    for (int kk = 0; kk < DD; kk += TK) {
        __syncthreads();
        #pragma unroll
        for (int p = 0; p < 4; p++) {
            int f = tid + p * 256;          // 0..1023
            int row = f >> 3;               // 0..127
            int k4 = (f & 7) * 4;           // 0..28
            float4 va = *(const float4*)(E + (size_t)(i0 + row) * DD + kk + k4);
            As[k4 + 0][row] = va.x; As[k4 + 1][row] = va.y;
            As[k4 + 2][row] = va.z; As[k4 + 3][row] = va.w;
            float4 vb = *(const float4*)(E + (size_t)(j0 + row) * DD + kk + k4);
            Bs[k4 + 0][row] = vb.x; Bs[k4 + 1][row] = vb.y;
            Bs[k4 + 2][row] = vb.z; Bs[k4 + 3][row] = vb.w;
        }
        __syncthreads();
        #pragma unroll
        for (int k = 0; k < TK; k++) {
            float4 a0 = *(const float4*)(&As[k][ty * 8]);
            float4 a1 = *(const float4*)(&As[k][ty * 8 + 4]);
            const ull* bp = (const ull*)(&Bs[k][tx * 8]);
            ull b2[4] = { bp[0], bp[1], bp[2], bp[3] };
            ull a2[8] = { pack2(a0.x, a0.x), pack2(a0.y, a0.y),
                          pack2(a0.z, a0.z), pack2(a0.w, a0.w),
                          pack2(a1.x, a1.x), pack2(a1.y, a1.y),
                          pack2(a1.z, a1.z), pack2(a1.w, a1.w) };
            #pragma unroll
            for (int r = 0; r < 8; r++)
                #pragma unroll
                for (int c = 0; c < 4; c++)
                    acc2[r][c] = fma2(a2[r], b2[c], acc2[r][c]);
        }
    }

    // unpack accumulators
    float acc[8][8];
    #pragma unroll
    for (int r = 0; r < 8; r++)
        #pragma unroll
        for (int c = 0; c < 4; c++)
            unpack2(acc2[r][c], acc[r][2 * c], acc[r][2 * c + 1]);

    const float deps = (float)DD * (EPSF * EPSF);

    // ---- row-side epilogue: rows i0+li over cols j0.. (slot bj*16+tx) ----
    #pragma unroll
    for (int r = 0; r < 8; r++) {
        int li = ty * 8 + r;
        float sqi = sSqI[li], si = sSI[li];
        unsigned pw = smPos[li][tx >> 2];
        unsigned nw = smNeg[li][tx >> 2];
        unsigned long long bp = 0ull;
        unsigned long long bn = 0xFFFFFFFFFFFFFFFFull;
        #pragma unroll
        for (int c = 0; c < 8; c++) {
            int jl = tx * 8 + c;
            float d2 = sqi + sSqJ[jl] - 2.0f * acc[r][c]
                     + 2.0f * EPSF * (si - sSJ[jl]) + deps;
            float dmv = sqrtf(fmaxf(d2, 0.0f));
            unsigned bits = __float_as_uint(dmv);
            unsigned j = (unsigned)(j0 + jl);
            if ((pw >> (jl & 31)) & 1u) {
                unsigned long long pk = ((unsigned long long)bits << 32) | (~j);
                if (pk > bp) bp = pk;               // ties: smaller j wins
            }
            if ((nw >> (jl & 31)) & 1u) {
                unsigned long long pk = ((unsigned long long)bits << 32) | j;
                if (pk < bn) bn = pk;
            }
        }
        size_t gi = (size_t)(i0 + li);
        g_posPart[gi * PART + bj * 16 + tx] = bp;
        g_negPart[gi * PART + bj * 16 + tx] = bn;
    }

    // ---- col-side epilogue: rows j0+jl over cols i0.. (slot bi*16+ty) ----
    if (!diag) {
        #pragma unroll
        for (int c = 0; c < 8; c++) {
            int jl = tx * 8 + c;
            float sqj = sSqJ[jl], sj = sSJ[jl];
            unsigned pw = smPos2[jl][ty >> 2];
            unsigned nw = smNeg2[jl][ty >> 2];
            unsigned long long bp = 0ull;
            unsigned long long bn = 0xFFFFFFFFFFFFFFFFull;
            #pragma unroll
            for (int r = 0; r < 8; r++) {
                int il = ty * 8 + r;
                float d2 = sqj + sSqI[il] - 2.0f * acc[r][c]
                         + 2.0f * EPSF * (sj - sSI[il]) + deps;   // eps sign: row = j
                float dmv = sqrtf(fmaxf(d2, 0.0f));
                unsigned bits = __float_as_uint(dmv);
                unsigned jx = (unsigned)(i0 + il);                // candidate col = i
                if ((pw >> (il & 31)) & 1u) {
                    unsigned long long pk = ((unsigned long long)bits << 32) | (~jx);
                    if (pk > bp) bp = pk;
                }
                if ((nw >> (il & 31)) & 1u) {
                    unsigned long long pk = ((unsigned long long)bits << 32) | jx;
                    if (pk < bn) bn = pk;
                }
            }
            size_t gj = (size_t)(j0 + jl);
            g_posPart[gj * PART + bi * 16 + ty] = bp;
            g_negPart[gj * PART + bi * 16 + ty] = bn;
        }
    }
}

// ---------------- kernel 3: per-row reduce + exact triplet loss ------------
__global__ void row_kernel(const float* __restrict__ E)
{
    int i = blockIdx.x;
    int t = threadIdx.x;            // 128 threads

    unsigned long long bp = 0ull, bn = 0xFFFFFFFFFFFFFFFFull;
    for (int p = t; p < PART; p += 128) {
        unsigned long long a = g_posPart[(size_t)i * PART + p]; if (a > bp) bp = a;
        unsigned long long b = g_negPart[(size_t)i * PART + p]; if (b < bn) bn = b;
    }
    #pragma unroll
    for (int o = 16; o; o >>= 1) {
        unsigned long long a = __shfl_down_sync(0xffffffffu, bp, o); if (a > bp) bp = a;
        unsigned long long b = __shfl_down_sync(0xffffffffu, bn, o); if (b < bn) bn = b;
    }
    __shared__ unsigned long long sp[4], sn[4], shP, shN;
    if ((t & 31) == 0) { sp[t >> 5] = bp; sn[t >> 5] = bn; }
    __syncthreads();
    if (t == 0) {
        bp = sp[0]; bn = sn[0];
        for (int w = 1; w < 4; w++) { if (sp[w] > bp) bp = sp[w]; if (sn[w] < bn) bn = sn[w]; }
        shP = bp; shN = bn;
    }
    __syncthreads();
    bp = shP; bn = shN;

    if (bp == 0ull || bn == 0xFFFFFFFFFFFFFFFFull) {   // invalid row
        if (t == 0) { g_loss[i] = 0.0f; g_w[i] = 0.0f; }
        return;
    }
    int pi = (int)(~(unsigned)bp) & (BN - 1);   // undo ~j
    int ni = (int)((unsigned)bn);

    float av = E[(size_t)i  * DD + t];
    float pv = E[(size_t)pi * DD + t];
    float nv = E[(size_t)ni * DD + t];
    float d1 = av - pv + EPSF;
    float d2 = av - nv + EPSF;
    float d3 = pv - nv + EPSF;
    float s1 = d1 * d1, s2 = d2 * d2, s3 = d3 * d3;
    #pragma unroll
    for (int o = 16; o; o >>= 1) {
        s1 += __shfl_down_sync(0xffffffffu, s1, o);
        s2 += __shfl_down_sync(0xffffffffu, s2, o);
        s3 += __shfl_down_sync(0xffffffffu, s3, o);
    }
    __shared__ float r1[4], r2[4], r3[4];
    if ((t & 31) == 0) { r1[t >> 5] = s1; r2[t >> 5] = s2; r3[t >> 5] = s3; }
    __syncthreads();
    if (t == 0) {
        float S1 = r1[0] + r1[1] + r1[2] + r1[3];
        float S2 = r2[0] + r2[1] + r2[2] + r2[3];
        float S3 = r3[0] + r3[1] + r3[2] + r3[3];
        float ap = sqrtf(S1), an = sqrtf(S2), pn = sqrtf(S3);
        float loss = fmaxf(ap - fminf(an, pn) + 1.0f, 0.0f);
        g_loss[i] = loss;
        g_w[i] = 1.0f;
    }
}

// ---------------- kernel 4: deterministic scalar reduction -----------------
__global__ void final_kernel(float* __restrict__ out)
{
    int t = threadIdx.x;            // 1024 threads
    float ls = 0.0f, ws = 0.0f;
    for (int r = t; r < BN; r += 1024) { ls += g_loss[r]; ws += g_w[r]; }
    #pragma unroll
    for (int o = 16; o; o >>= 1) {
        ls += __shfl_down_sync(0xffffffffu, ls, o);
        ws += __shfl_down_sync(0xffffffffu, ws, o);
    }
    __shared__ float sl[32], sw[32];
    if ((t & 31) == 0) { sl[t >> 5] = ls; sw[t >> 5] = ws; }
    __syncthreads();
    if (t == 0) {
        float L = 0.0f, W = 0.0f;
        for (int w = 0; w < 32; w++) { L += sl[w]; W += sw[w]; }
        out[0] = L / fmaxf(W, 1.0f);
    }
}

// ---------------- launch ----------------------------------------------------
extern "C" void kernel_launch(void* const* d_in, const int* in_sizes, int n_in,
                              void* d_out, int out_size)
{
    const float*    E   = (const float*)d_in[0];
    const int*      tgt = (const int*)d_in[1];
    const unsigned* P   = (const unsigned*)d_in[2];
    const unsigned* N   = (const unsigned*)d_in[3];
    float* out = (float*)d_out;

    prep_kernel<<<BN, 128>>>(E, tgt, P, N);
    main_kernel<<<NBLK, 256>>>(E);
    row_kernel<<<BN, 128>>>(E);
    final_kernel<<<1, 1024>>>(out);
}

// round 13
// speedup vs baseline: 2.0985x; 1.1340x over previous
#include <cuda_runtime.h>
#include <stdint.h>

#define BN 4096
#define DD 128
#define EPSF 1e-6f
#define NWORDS (BN/32)        // 128 words per row
#define PART 512              // 32 "other-tile" slots * 16 lane slots per row
#define TK 32                 // K chunk
#define NT 32                 // 32 row/col tiles
#define NBLK 528              // NT*(NT+1)/2 upper-triangular blocks
#define RPB 8                 // rows per block in mask kernel

// ---------------- device scratch (static; no allocations allowed) ----------
__device__ float g_sq[BN];
__device__ float g_s[BN];
__device__ unsigned g_posbits[BN * NWORDS];
__device__ unsigned g_negbits[BN * NWORDS];
__device__ unsigned long long g_posPart[(size_t)BN * PART];
__device__ unsigned long long g_negPart[(size_t)BN * PART];
__device__ float g_loss[BN];
__device__ float g_w[BN];

// ---------------- f32x2 helpers (sm_100+ base ISA) --------------------------
typedef unsigned long long ull;
__device__ __forceinline__ ull fma2(ull a, ull b, ull c) {
    ull d;
    asm("fma.rn.f32x2 %0, %1, %2, %3;" : "=l"(d) : "l"(a), "l"(b), "l"(c));
    return d;
}
__device__ __forceinline__ ull pack2(float lo, float hi) {
    ull d;
    asm("mov.b64 %0, {%1, %2};" : "=l"(d) : "f"(lo), "f"(hi));
    return d;
}
__device__ __forceinline__ void unpack2(ull v, float& lo, float& hi) {
    asm("mov.b64 {%0, %1}, %2;" : "=f"(lo), "=f"(hi) : "l"(v));
}

// ---------------- kernel 0: row sums ----------------------------------------
__global__ void rowstat_kernel(const float* __restrict__ E)
{
    int i = blockIdx.x;
    int t = threadIdx.x;            // 128 threads
    float v = E[(size_t)i * DD + t];
    float s = v, q = v * v;
    #pragma unroll
    for (int o = 16; o; o >>= 1) {
        s += __shfl_down_sync(0xffffffffu, s, o);
        q += __shfl_down_sync(0xffffffffu, q, o);
    }
    __shared__ float ss[4], qq[4];
    if ((t & 31) == 0) { ss[t >> 5] = s; qq[t >> 5] = q; }
    __syncthreads();
    if (t == 0) {
        g_s[i]  = ss[0] + ss[1] + ss[2] + ss[3];
        g_sq[i] = qq[0] + qq[1] + qq[2] + qq[3];
    }
}

// ---------------- kernel 1: ballot-pack + smem permute of masks -------------
// Masks are 4-byte bool elements; nonzero <=> true.
// Output bit u of word w for row i = mask[i][tgt[w*32+u]]  (same as before).
__global__ __launch_bounds__(256)
void mask_kernel(const int* __restrict__ tgt,
                 const unsigned* __restrict__ P,
                 const unsigned* __restrict__ N)
{
    __shared__ int sTgt[BN];                 // 16 KB
    __shared__ unsigned sP[NWORDS], sN[NWORDS];

    const int tid = threadIdx.x;
    const int lane = tid & 31, warp = tid >> 5;

    for (int m = tid; m < BN; m += 256) sTgt[m] = tgt[m];

    for (int r = 0; r < RPB; r++) {
        const int i = blockIdx.x * RPB + r;
        __syncthreads();                     // sTgt ready / sP,sN reuse safe

        // coalesced ballot-pack: word c bit l = (mask[i][c*32+l] != 0)
        for (int c = warp; c < NWORDS; c += 8) {
            unsigned pv = P[(size_t)i * BN + c * 32 + lane];
            unsigned nv = N[(size_t)i * BN + c * 32 + lane];
            unsigned pb = __ballot_sync(0xffffffffu, pv != 0u);
            unsigned nb = __ballot_sync(0xffffffffu, nv != 0u);
            if (lane == 0) { sP[c] = pb; sN[c] = nb; }
        }
        __syncthreads();

        // permute in smem: threads 0-127 do pos words, 128-255 neg words.
        // staggered bit order (b = (u+wd)&31) -> conflict-free sTgt LDS.
        const int wd = tid & 127;
        const unsigned* src = (tid < 128) ? sP : sN;
        unsigned out = 0u;
        #pragma unroll
        for (int u = 0; u < 32; u++) {
            int b  = (u + wd) & 31;
            int tj = sTgt[wd * 32 + b];
            out |= ((src[tj >> 5] >> (tj & 31)) & 1u) << b;
        }
        if (tid < 128) g_posbits[i * NWORDS + wd] = out;
        else           g_negbits[i * NWORDS + wd] = out;
    }
}

// ---------------- kernel 2: symmetric tiled SGEMM (f32x2) + dual epilogue --
__device__ __forceinline__ int tri_off(int k) { return k * 32 - (k * (k - 1)) / 2; }

__global__ __launch_bounds__(256, 2)
void main_kernel(const float* __restrict__ E)
{
    __shared__ float As[TK][132];   // [k][i]
    __shared__ float Bs[TK][132];   // [k][j]
    __shared__ float sSqI[128], sSI[128], sSqJ[128], sSJ[128];
    __shared__ unsigned smPos[128][4], smNeg[128][4];    // i-rows @ j-range
    __shared__ unsigned smPos2[128][4], smNeg2[128][4];  // j-rows @ i-range

    const int tid = threadIdx.x;
    const int tx = tid & 15;        // j direction
    const int ty = tid >> 4;        // i direction

    // triangular decode: block t -> (bi, bj), bi <= bj
    const int tblk = blockIdx.x;
    int bi = (int)floorf((65.0f - sqrtf(4225.0f - 8.0f * (float)tblk)) * 0.5f);
    if (bi < 0) bi = 0; if (bi > 31) bi = 31;
    while (tri_off(bi + 1) <= tblk) bi++;
    while (tri_off(bi) > tblk) bi--;
    const int bj = bi + (tblk - tri_off(bi));
    const int i0 = bi * 128;
    const int j0 = bj * 128;
    const bool diag = (bi == bj);

    if (tid < 128) {
        sSqI[tid] = g_sq[i0 + tid]; sSI[tid] = g_s[i0 + tid];
        sSqJ[tid] = g_sq[j0 + tid]; sSJ[tid] = g_s[j0 + tid];
    }
    for (int m = tid; m < 512; m += 256) {
        int r = m >> 2, w = m & 3;
        smPos [r][w] = g_posbits[(i0 + r) * NWORDS + (j0 >> 5) + w];
        smNeg [r][w] = g_negbits[(i0 + r) * NWORDS + (j0 >> 5) + w];
        smPos2[r][w] = g_posbits[(j0 + r) * NWORDS + (i0 >> 5) + w];
        smNeg2[r][w] = g_negbits[(j0 + r) * NWORDS + (i0 >> 5) + w];
    }

    ull acc2[8][4];                 // 8 i-rows x 4 j-pairs (f32x2)
    #pragma unroll
    for (int r = 0; r < 8; r++)
        #pragma unroll
        for (int c = 0; c < 4; c++) acc2[r][c] = 0ull;

    for (int kk = 0; kk < DD; kk += TK) {
        __syncthreads();
        #pragma unroll
        for (int p = 0; p < 4; p++) {
            int f = tid + p * 256;          // 0..1023
            int row = f >> 3;               // 0..127
            int k4 = (f & 7) * 4;           // 0..28
            float4 va = *(const float4*)(E + (size_t)(i0 + row) * DD + kk + k4);
            As[k4 + 0][row] = va.x; As[k4 + 1][row] = va.y;
            As[k4 + 2][row] = va.z; As[k4 + 3][row] = va.w;
            float4 vb = *(const float4*)(E + (size_t)(j0 + row) * DD + kk + k4);
            Bs[k4 + 0][row] = vb.x; Bs[k4 + 1][row] = vb.y;
            Bs[k4 + 2][row] = vb.z; Bs[k4 + 3][row] = vb.w;
        }
        __syncthreads();
        #pragma unroll
        for (int k = 0; k < TK; k++) {
            float4 a0 = *(const float4*)(&As[k][ty * 8]);
            float4 a1 = *(const float4*)(&As[k][ty * 8 + 4]);
            const ull* bp = (const ull*)(&Bs[k][tx * 8]);
            ull b2[4] = { bp[0], bp[1], bp[2], bp[3] };
            ull a2[8] = { pack2(a0.x, a0.x), pack2(a0.y, a0.y),
                          pack2(a0.z, a0.z), pack2(a0.w, a0.w),
                          pack2(a1.x, a1.x), pack2(a1.y, a1.y),
                          pack2(a1.z, a1.z), pack2(a1.w, a1.w) };
            #pragma unroll
            for (int r = 0; r < 8; r++)
                #pragma unroll
                for (int c = 0; c < 4; c++)
                    acc2[r][c] = fma2(a2[r], b2[c], acc2[r][c]);
        }
    }

    // unpack accumulators
    float acc[8][8];
    #pragma unroll
    for (int r = 0; r < 8; r++)
        #pragma unroll
        for (int c = 0; c < 4; c++)
            unpack2(acc2[r][c], acc[r][2 * c], acc[r][2 * c + 1]);

    const float deps = (float)DD * (EPSF * EPSF);

    // ---- row-side epilogue: rows i0+li over cols j0.. (slot bj*16+tx) ----
    #pragma unroll
    for (int r = 0; r < 8; r++) {
        int li = ty * 8 + r;
        float sqi = sSqI[li], si = sSI[li];
        unsigned pw = smPos[li][tx >> 2];
        unsigned nw = smNeg[li][tx >> 2];
        unsigned long long bp = 0ull;
        unsigned long long bn = 0xFFFFFFFFFFFFFFFFull;
        #pragma unroll
        for (int c = 0; c < 8; c++) {
            int jl = tx * 8 + c;
            float d2 = sqi + sSqJ[jl] - 2.0f * acc[r][c]
                     + 2.0f * EPSF * (si - sSJ[jl]) + deps;
            float dmv = sqrtf(fmaxf(d2, 0.0f));
            unsigned bits = __float_as_uint(dmv);
            unsigned j = (unsigned)(j0 + jl);
            if ((pw >> (jl & 31)) & 1u) {
                unsigned long long pk = ((unsigned long long)bits << 32) | (~j);
                if (pk > bp) bp = pk;               // ties: smaller j wins
            }
            if ((nw >> (jl & 31)) & 1u) {
                unsigned long long pk = ((unsigned long long)bits << 32) | j;
                if (pk < bn) bn = pk;
            }
        }
        size_t gi = (size_t)(i0 + li);
        g_posPart[gi * PART + bj * 16 + tx] = bp;
        g_negPart[gi * PART + bj * 16 + tx] = bn;
    }

    // ---- col-side epilogue: rows j0+jl over cols i0.. (slot bi*16+ty) ----
    if (!diag) {
        #pragma unroll
        for (int c = 0; c < 8; c++) {
            int jl = tx * 8 + c;
            float sqj = sSqJ[jl], sj = sSJ[jl];
            unsigned pw = smPos2[jl][ty >> 2];
            unsigned nw = smNeg2[jl][ty >> 2];
            unsigned long long bp = 0ull;
            unsigned long long bn = 0xFFFFFFFFFFFFFFFFull;
            #pragma unroll
            for (int r = 0; r < 8; r++) {
                int il = ty * 8 + r;
                float d2 = sqj + sSqI[il] - 2.0f * acc[r][c]
                         + 2.0f * EPSF * (sj - sSI[il]) + deps;   // eps sign: row = j
                float dmv = sqrtf(fmaxf(d2, 0.0f));
                unsigned bits = __float_as_uint(dmv);
                unsigned jx = (unsigned)(i0 + il);                // candidate col = i
                if ((pw >> (il & 31)) & 1u) {
                    unsigned long long pk = ((unsigned long long)bits << 32) | (~jx);
                    if (pk > bp) bp = pk;
                }
                if ((nw >> (il & 31)) & 1u) {
                    unsigned long long pk = ((unsigned long long)bits << 32) | jx;
                    if (pk < bn) bn = pk;
                }
            }
            size_t gj = (size_t)(j0 + jl);
            g_posPart[gj * PART + bi * 16 + ty] = bp;
            g_negPart[gj * PART + bi * 16 + ty] = bn;
        }
    }
}

// ---------------- kernel 3: per-row reduce + exact triplet loss ------------
__global__ void row_kernel(const float* __restrict__ E)
{
    int i = blockIdx.x;
    int t = threadIdx.x;            // 128 threads

    unsigned long long bp = 0ull, bn = 0xFFFFFFFFFFFFFFFFull;
    for (int p = t; p < PART; p += 128) {
        unsigned long long a = g_posPart[(size_t)i * PART + p]; if (a > bp) bp = a;
        unsigned long long b = g_negPart[(size_t)i * PART + p]; if (b < bn) bn = b;
    }
    #pragma unroll
    for (int o = 16; o; o >>= 1) {
        unsigned long long a = __shfl_down_sync(0xffffffffu, bp, o); if (a > bp) bp = a;
        unsigned long long b = __shfl_down_sync(0xffffffffu, bn, o); if (b < bn) bn = b;
    }
    __shared__ unsigned long long sp[4], sn[4], shP, shN;
    if ((t & 31) == 0) { sp[t >> 5] = bp; sn[t >> 5] = bn; }
    __syncthreads();
    if (t == 0) {
        bp = sp[0]; bn = sn[0];
        for (int w = 1; w < 4; w++) { if (sp[w] > bp) bp = sp[w]; if (sn[w] < bn) bn = sn[w]; }
        shP = bp; shN = bn;
    }
    __syncthreads();
    bp = shP; bn = shN;

    if (bp == 0ull || bn == 0xFFFFFFFFFFFFFFFFull) {   // invalid row
        if (t == 0) { g_loss[i] = 0.0f; g_w[i] = 0.0f; }
        return;
    }
    int pi = (int)(~(unsigned)bp) & (BN - 1);   // undo ~j
    int ni = (int)((unsigned)bn);

    float av = E[(size_t)i  * DD + t];
    float pv = E[(size_t)pi * DD + t];
    float nv = E[(size_t)ni * DD + t];
    float d1 = av - pv + EPSF;
    float d2 = av - nv + EPSF;
    float d3 = pv - nv + EPSF;
    float s1 = d1 * d1, s2 = d2 * d2, s3 = d3 * d3;
    #pragma unroll
    for (int o = 16; o; o >>= 1) {
        s1 += __shfl_down_sync(0xffffffffu, s1, o);
        s2 += __shfl_down_sync(0xffffffffu, s2, o);
        s3 += __shfl_down_sync(0xffffffffu, s3, o);
    }
    __shared__ float r1[4], r2[4], r3[4];
    if ((t & 31) == 0) { r1[t >> 5] = s1; r2[t >> 5] = s2; r3[t >> 5] = s3; }
    __syncthreads();
    if (t == 0) {
        float S1 = r1[0] + r1[1] + r1[2] + r1[3];
        float S2 = r2[0] + r2[1] + r2[2] + r2[3];
        float S3 = r3[0] + r3[1] + r3[2] + r3[3];
        float ap = sqrtf(S1), an = sqrtf(S2), pn = sqrtf(S3);
        float loss = fmaxf(ap - fminf(an, pn) + 1.0f, 0.0f);
        g_loss[i] = loss;
        g_w[i] = 1.0f;
    }
}

// ---------------- kernel 4: deterministic scalar reduction -----------------
__global__ void final_kernel(float* __restrict__ out)
{
    int t = threadIdx.x;            // 1024 threads
    float ls = 0.0f, ws = 0.0f;
    for (int r = t; r < BN; r += 1024) { ls += g_loss[r]; ws += g_w[r]; }
    #pragma unroll
    for (int o = 16; o; o >>= 1) {
        ls += __shfl_down_sync(0xffffffffu, ls, o);
        ws += __shfl_down_sync(0xffffffffu, ws, o);
    }
    __shared__ float sl[32], sw[32];
    if ((t & 31) == 0) { sl[t >> 5] = ls; sw[t >> 5] = ws; }
    __syncthreads();
    if (t == 0) {
        float L = 0.0f, W = 0.0f;
        for (int w = 0; w < 32; w++) { L += sl[w]; W += sw[w]; }
        out[0] = L / fmaxf(W, 1.0f);
    }
}

// ---------------- launch ----------------------------------------------------
extern "C" void kernel_launch(void* const* d_in, const int* in_sizes, int n_in,
                              void* d_out, int out_size)
{
    const float*    E   = (const float*)d_in[0];
    const int*      tgt = (const int*)d_in[1];
    const unsigned* P   = (const unsigned*)d_in[2];
    const unsigned* N   = (const unsigned*)d_in[3];
    float* out = (float*)d_out;

    rowstat_kernel<<<BN, 128>>>(E);
    mask_kernel<<<BN / RPB, 256>>>(tgt, P, N);
    main_kernel<<<NBLK, 256>>>(E);
    row_kernel<<<BN, 128>>>(E);
    final_kernel<<<1, 1024>>>(out);
}

// round 14
// speedup vs baseline: 2.1334x; 1.0166x over previous
#include <cuda_runtime.h>
#include <stdint.h>

#define BN 4096
#define DD 128
#define EPSF 1e-6f
#define NWORDS (BN/32)        // 128 words per row
#define PART 32               // one reduced slot per "other tile" per row
#define TK 32                 // K chunk
#define NT 32                 // 32 row/col tiles
#define NBLK 528              // NT*(NT+1)/2 upper-triangular blocks
#define RPB 8                 // rows per block in mask kernel
#define TILEF 16896           // TK*132*4 bytes, one smem tile

// ---------------- device scratch (static; no allocations allowed) ----------
__device__ float g_sq[BN];
__device__ float g_s[BN];
__device__ unsigned g_posbits[BN * NWORDS];
__device__ unsigned g_negbits[BN * NWORDS];
__device__ unsigned long long g_posPart[(size_t)BN * PART];
__device__ unsigned long long g_negPart[(size_t)BN * PART];
__device__ float g_loss[BN];
__device__ float g_w[BN];

// ---------------- f32x2 helpers (sm_100+ base ISA) --------------------------
typedef unsigned long long ull;
__device__ __forceinline__ ull fma2(ull a, ull b, ull c) {
    ull d;
    asm("fma.rn.f32x2 %0, %1, %2, %3;" : "=l"(d) : "l"(a), "l"(b), "l"(c));
    return d;
}
__device__ __forceinline__ ull pack2(float lo, float hi) {
    ull d;
    asm("mov.b64 %0, {%1, %2};" : "=l"(d) : "f"(lo), "f"(hi));
    return d;
}
__device__ __forceinline__ void unpack2(ull v, float& lo, float& hi) {
    asm("mov.b64 {%0, %1}, %2;" : "=f"(lo), "=f"(hi) : "l"(v));
}

// ---------------- kernel 0: row sums ----------------------------------------
__global__ void rowstat_kernel(const float* __restrict__ E)
{
    int i = blockIdx.x;
    int t = threadIdx.x;            // 128 threads
    float v = E[(size_t)i * DD + t];
    float s = v, q = v * v;
    #pragma unroll
    for (int o = 16; o; o >>= 1) {
        s += __shfl_down_sync(0xffffffffu, s, o);
        q += __shfl_down_sync(0xffffffffu, q, o);
    }
    __shared__ float ss[4], qq[4];
    if ((t & 31) == 0) { ss[t >> 5] = s; qq[t >> 5] = q; }
    __syncthreads();
    if (t == 0) {
        g_s[i]  = ss[0] + ss[1] + ss[2] + ss[3];
        g_sq[i] = qq[0] + qq[1] + qq[2] + qq[3];
    }
}

// ---------------- kernel 1: ballot-pack + smem permute of masks -------------
__global__ __launch_bounds__(256)
void mask_kernel(const int* __restrict__ tgt,
                 const unsigned* __restrict__ P,
                 const unsigned* __restrict__ N)
{
    __shared__ int sTgt[BN];                 // 16 KB
    __shared__ unsigned sP[NWORDS], sN[NWORDS];

    const int tid = threadIdx.x;
    const int lane = tid & 31, warp = tid >> 5;

    for (int m = tid; m < BN; m += 256) sTgt[m] = tgt[m];

    for (int r = 0; r < RPB; r++) {
        const int i = blockIdx.x * RPB + r;
        __syncthreads();                     // sTgt ready / sP,sN reuse safe

        // coalesced ballot-pack: word c bit l = (mask[i][c*32+l] != 0)
        for (int c = warp; c < NWORDS; c += 8) {
            unsigned pv = P[(size_t)i * BN + c * 32 + lane];
            unsigned nv = N[(size_t)i * BN + c * 32 + lane];
            unsigned pb = __ballot_sync(0xffffffffu, pv != 0u);
            unsigned nb = __ballot_sync(0xffffffffu, nv != 0u);
            if (lane == 0) { sP[c] = pb; sN[c] = nb; }
        }
        __syncthreads();

        // permute in smem; staggered bit order -> conflict-free sTgt LDS
        const int wd = tid & 127;
        const unsigned* src = (tid < 128) ? sP : sN;
        unsigned out = 0u;
        #pragma unroll
        for (int u = 0; u < 32; u++) {
            int b  = (u + wd) & 31;
            int tj = sTgt[wd * 32 + b];
            out |= ((src[tj >> 5] >> (tj & 31)) & 1u) << b;
        }
        if (tid < 128) g_posbits[i * NWORDS + wd] = out;
        else           g_negbits[i * NWORDS + wd] = out;
    }
}

// ---------------- kernel 2: symmetric tiled SGEMM (f32x2) + dual epilogue --
__device__ __forceinline__ int tri_off(int k) { return k * 32 - (k * (k - 1)) / 2; }

__global__ __launch_bounds__(256, 2)
void main_kernel(const float* __restrict__ E)
{
    // As/Bs (mainloop) and pos/neg stage arrays (epilogue) share storage.
    __shared__ __align__(16) char uS[2 * TILEF];
    __shared__ float sSqI[128], sSI[128], sSqJ[128], sSJ[128];
    __shared__ unsigned smPos[128][4], smNeg[128][4];    // i-rows @ j-range
    __shared__ unsigned smPos2[128][4], smNeg2[128][4];  // j-rows @ i-range

    float (*As)[132] = (float (*)[132])uS;
    float (*Bs)[132] = (float (*)[132])(uS + TILEF);
    ull (*stP)[16] = (ull (*)[16])uS;             // 128*16*8 = 16384 <= TILEF
    ull (*stN)[16] = (ull (*)[16])(uS + TILEF);

    const int tid = threadIdx.x;
    const int tx = tid & 15;        // j direction
    const int ty = tid >> 4;        // i direction

    // triangular decode: block t -> (bi, bj), bi <= bj
    const int tblk = blockIdx.x;
    int bi = (int)floorf((65.0f - sqrtf(4225.0f - 8.0f * (float)tblk)) * 0.5f);
    if (bi < 0) bi = 0; if (bi > 31) bi = 31;
    while (tri_off(bi + 1) <= tblk) bi++;
    while (tri_off(bi) > tblk) bi--;
    const int bj = bi + (tblk - tri_off(bi));
    const int i0 = bi * 128;
    const int j0 = bj * 128;
    const bool diag = (bi == bj);

    if (tid < 128) {
        sSqI[tid] = g_sq[i0 + tid]; sSI[tid] = g_s[i0 + tid];
        sSqJ[tid] = g_sq[j0 + tid]; sSJ[tid] = g_s[j0 + tid];
    }
    for (int m = tid; m < 512; m += 256) {
        int r = m >> 2, w = m & 3;
        smPos [r][w] = g_posbits[(i0 + r) * NWORDS + (j0 >> 5) + w];
        smNeg [r][w] = g_negbits[(i0 + r) * NWORDS + (j0 >> 5) + w];
        smPos2[r][w] = g_posbits[(j0 + r) * NWORDS + (i0 >> 5) + w];
        smNeg2[r][w] = g_negbits[(j0 + r) * NWORDS + (i0 >> 5) + w];
    }

    ull acc2[8][4];                 // 8 i-rows x 4 j-pairs (f32x2)
    #pragma unroll
    for (int r = 0; r < 8; r++)
        #pragma unroll
        for (int c = 0; c < 4; c++) acc2[r][c] = 0ull;

    for (int kk = 0; kk < DD; kk += TK) {
        __syncthreads();
        #pragma unroll
        for (int p = 0; p < 4; p++) {
            int f = tid + p * 256;          // 0..1023
            int row = f >> 3;               // 0..127
            int k4 = (f & 7) * 4;           // 0..28
            float4 va = *(const float4*)(E + (size_t)(i0 + row) * DD + kk + k4);
            As[k4 + 0][row] = va.x; As[k4 + 1][row] = va.y;
            As[k4 + 2][row] = va.z; As[k4 + 3][row] = va.w;
            float4 vb = *(const float4*)(E + (size_t)(j0 + row) * DD + kk + k4);
            Bs[k4 + 0][row] = vb.x; Bs[k4 + 1][row] = vb.y;
            Bs[k4 + 2][row] = vb.z; Bs[k4 + 3][row] = vb.w;
        }
        __syncthreads();
        #pragma unroll
        for (int k = 0; k < TK; k++) {
            float4 a0 = *(const float4*)(&As[k][ty * 8]);
            float4 a1 = *(const float4*)(&As[k][ty * 8 + 4]);
            const ull* bp = (const ull*)(&Bs[k][tx * 8]);
            ull b2[4] = { bp[0], bp[1], bp[2], bp[3] };
            ull a2[8] = { pack2(a0.x, a0.x), pack2(a0.y, a0.y),
                          pack2(a0.z, a0.z), pack2(a0.w, a0.w),
                          pack2(a1.x, a1.x), pack2(a1.y, a1.y),
                          pack2(a1.z, a1.z), pack2(a1.w, a1.w) };
            #pragma unroll
            for (int r = 0; r < 8; r++)
                #pragma unroll
                for (int c = 0; c < 4; c++)
                    acc2[r][c] = fma2(a2[r], b2[c], acc2[r][c]);
        }
    }

    // unpack accumulators
    float acc[8][8];
    #pragma unroll
    for (int r = 0; r < 8; r++)
        #pragma unroll
        for (int c = 0; c < 4; c++)
            unpack2(acc2[r][c], acc[r][2 * c], acc[r][2 * c + 1]);

    const float deps = (float)DD * (EPSF * EPSF);
    __syncthreads();                 // all done reading As/Bs -> reuse as stage

    // ---- row-side: rows i0+li over cols j0..; in-block reduce to slot bj ----
    #pragma unroll
    for (int r = 0; r < 8; r++) {
        int li = ty * 8 + r;
        float sqi = sSqI[li], si = sSI[li];
        unsigned pw = smPos[li][tx >> 2];
        unsigned nw = smNeg[li][tx >> 2];
        ull bp = 0ull, bn = 0xFFFFFFFFFFFFFFFFull;
        #pragma unroll
        for (int c = 0; c < 8; c++) {
            int jl = tx * 8 + c;
            float d2 = sqi + sSqJ[jl] - 2.0f * acc[r][c]
                     + 2.0f * EPSF * (si - sSJ[jl]) + deps;
            float dmv = sqrtf(fmaxf(d2, 0.0f));
            unsigned bits = __float_as_uint(dmv);
            unsigned j = (unsigned)(j0 + jl);
            if ((pw >> (jl & 31)) & 1u) {
                ull pk = ((ull)bits << 32) | (~j);
                if (pk > bp) bp = pk;               // ties: smaller j wins
            }
            if ((nw >> (jl & 31)) & 1u) {
                ull pk = ((ull)bits << 32) | j;
                if (pk < bn) bn = pk;
            }
        }
        stP[li][tx] = bp;
        stN[li][tx] = bn;
    }
    __syncthreads();
    {
        int li = tid & 127;
        if (tid < 128) {
            ull m = 0ull;
            #pragma unroll
            for (int k = 0; k < 16; k++) {
                ull v = stP[li][(li + k) & 15]; if (v > m) m = v;
            }
            g_posPart[(size_t)(i0 + li) * PART + bj] = m;
        } else {
            ull m = 0xFFFFFFFFFFFFFFFFull;
            #pragma unroll
            for (int k = 0; k < 16; k++) {
                ull v = stN[li][(li + k) & 15]; if (v < m) m = v;
            }
            g_negPart[(size_t)(i0 + li) * PART + bj] = m;
        }
    }

    // ---- col-side: rows j0+jl over cols i0..; slot bi ----
    if (!diag) {
        __syncthreads();
        #pragma unroll
        for (int c = 0; c < 8; c++) {
            int jl = tx * 8 + c;
            float sqj = sSqJ[jl], sj = sSJ[jl];
            unsigned pw = smPos2[jl][ty >> 2];
            unsigned nw = smNeg2[jl][ty >> 2];
            ull bp = 0ull, bn = 0xFFFFFFFFFFFFFFFFull;
            #pragma unroll
            for (int r = 0; r < 8; r++) {
                int il = ty * 8 + r;
                float d2 = sqj + sSqI[il] - 2.0f * acc[r][c]
                         + 2.0f * EPSF * (sj - sSI[il]) + deps;   // eps sign: row = j
                float dmv = sqrtf(fmaxf(d2, 0.0f));
                unsigned bits = __float_as_uint(dmv);
                unsigned jx = (unsigned)(i0 + il);                // candidate col = i
                if ((pw >> (il & 31)) & 1u) {
                    ull pk = ((ull)bits << 32) | (~jx);
                    if (pk > bp) bp = pk;
                }
                if ((nw >> (il & 31)) & 1u) {
                    ull pk = ((ull)bits << 32) | jx;
                    if (pk < bn) bn = pk;
                }
            }
            stP[jl][ty] = bp;
            stN[jl][ty] = bn;
        }
        __syncthreads();
        {
            int jl = tid & 127;
            if (tid < 128) {
                ull m = 0ull;
                #pragma unroll
                for (int k = 0; k < 16; k++) {
                    ull v = stP[jl][(jl + k) & 15]; if (v > m) m = v;
                }
                g_posPart[(size_t)(j0 + jl) * PART + bi] = m;
            } else {
                ull m = 0xFFFFFFFFFFFFFFFFull;
                #pragma unroll
                for (int k = 0; k < 16; k++) {
                    ull v = stN[jl][(jl + k) & 15]; if (v < m) m = v;
                }
                g_negPart[(size_t)(j0 + jl) * PART + bi] = m;
            }
        }
    }
}

// ---------------- kernel 3: per-row reduce + exact triplet loss ------------
__global__ void row_kernel(const float* __restrict__ E)
{
    int i = blockIdx.x;
    int t = threadIdx.x;            // 128 threads

    ull bp = 0ull, bn = 0xFFFFFFFFFFFFFFFFull;
    if (t < PART) {
        bp = g_posPart[(size_t)i * PART + t];
        bn = g_negPart[(size_t)i * PART + t];
    }
    #pragma unroll
    for (int o = 16; o; o >>= 1) {
        ull a = __shfl_down_sync(0xffffffffu, bp, o); if (a > bp) bp = a;
        ull b = __shfl_down_sync(0xffffffffu, bn, o); if (b < bn) bn = b;
    }
    __shared__ ull shP, shN;
    if (t == 0) { shP = bp; shN = bn; }
    __syncthreads();
    bp = shP; bn = shN;

    if (bp == 0ull || bn == 0xFFFFFFFFFFFFFFFFull) {   // invalid row
        if (t == 0) { g_loss[i] = 0.0f; g_w[i] = 0.0f; }
        return;
    }
    int pi = (int)(~(unsigned)bp) & (BN - 1);   // undo ~j
    int ni = (int)((unsigned)bn);

    float av = E[(size_t)i  * DD + t];
    float pv = E[(size_t)pi * DD + t];
    float nv = E[(size_t)ni * DD + t];
    float d1 = av - pv + EPSF;
    float d2 = av - nv + EPSF;
    float d3 = pv - nv + EPSF;
    float s1 = d1 * d1, s2 = d2 * d2, s3 = d3 * d3;
    #pragma unroll
    for (int o = 16; o; o >>= 1) {
        s1 += __shfl_down_sync(0xffffffffu, s1, o);
        s2 += __shfl_down_sync(0xffffffffu, s2, o);
        s3 += __shfl_down_sync(0xffffffffu, s3, o);
    }
    __shared__ float r1[4], r2[4], r3[4];
    if ((t & 31) == 0) { r1[t >> 5] = s1; r2[t >> 5] = s2; r3[t >> 5] = s3; }
    __syncthreads();
    if (t == 0) {
        float S1 = r1[0] + r1[1] + r1[2] + r1[3];
        float S2 = r2[0] + r2[1] + r2[2] + r2[3];
        float S3 = r3[0] + r3[1] + r3[2] + r3[3];
        float ap = sqrtf(S1), an = sqrtf(S2), pn = sqrtf(S3);
        float loss = fmaxf(ap - fminf(an, pn) + 1.0f, 0.0f);
        g_loss[i] = loss;
        g_w[i] = 1.0f;
    }
}

// ---------------- kernel 4: deterministic scalar reduction -----------------
__global__ void final_kernel(float* __restrict__ out)
{
    int t = threadIdx.x;            // 1024 threads
    float ls = 0.0f, ws = 0.0f;
    for (int r = t; r < BN; r += 1024) { ls += g_loss[r]; ws += g_w[r]; }
    #pragma unroll
    for (int o = 16; o; o >>= 1) {
        ls += __shfl_down_sync(0xffffffffu, ls, o);
        ws += __shfl_down_sync(0xffffffffu, ws, o);
    }
    __shared__ float sl[32], sw[32];
    if ((t & 31) == 0) { sl[t >> 5] = ls; sw[t >> 5] = ws; }
    __syncthreads();
    if (t == 0) {
        float L = 0.0f, W = 0.0f;
        for (int w = 0; w < 32; w++) { L += sl[w]; W += sw[w]; }
        out[0] = L / fmaxf(W, 1.0f);
    }
}

// ---------------- launch ----------------------------------------------------
extern "C" void kernel_launch(void* const* d_in, const int* in_sizes, int n_in,
                              void* d_out, int out_size)
{
    const float*    E   = (const float*)d_in[0];
    const int*      tgt = (const int*)d_in[1];
    const unsigned* P   = (const unsigned*)d_in[2];
    const unsigned* N   = (const unsigned*)d_in[3];
    float* out = (float*)d_out;

    rowstat_kernel<<<BN, 128>>>(E);
    mask_kernel<<<BN / RPB, 256>>>(tgt, P, N);
    main_kernel<<<NBLK, 256>>>(E);
    row_kernel<<<BN, 128>>>(E);
    final_kernel<<<1, 1024>>>(out);
}

// round 15
// speedup vs baseline: 2.2141x; 1.0378x over previous
#include <cuda_runtime.h>
#include <stdint.h>

#define BN 4096
#define DD 128
#define EPSF 1e-6f
#define NWORDS (BN/32)        // 128 words per row
#define PART 32               // one reduced slot per "other tile" per row
#define TK 32                 // K chunk
#define NT 32                 // 32 row/col tiles
#define NBLK 528              // NT*(NT+1)/2 upper-triangular blocks
#define RPB 8                 // rows per block in mask kernel
#define LDA 132               // padded smem row (floats)
#define CHUNKF (TK * LDA * 4) // 16896 B: one matrix chunk
#define BUFB (2 * CHUNKF)     // A+B for one stage
#define DSMEM (2 * BUFB)      // double buffered: 67584 B

// ---------------- device scratch (static; no allocations allowed) ----------
__device__ float g_ET[DD * BN];          // transposed embedding [k][i]
__device__ float g_sq[BN];
__device__ float g_s[BN];
__device__ unsigned g_posbits[BN * NWORDS];
__device__ unsigned g_negbits[BN * NWORDS];
__device__ unsigned long long g_posPart[(size_t)BN * PART];
__device__ unsigned long long g_negPart[(size_t)BN * PART];
__device__ float g_loss[BN];
__device__ float g_w[BN];

// ---------------- helpers ----------------------------------------------------
typedef unsigned long long ull;
__device__ __forceinline__ ull fma2(ull a, ull b, ull c) {
    ull d;
    asm("fma.rn.f32x2 %0, %1, %2, %3;" : "=l"(d) : "l"(a), "l"(b), "l"(c));
    return d;
}
__device__ __forceinline__ ull pack2(float lo, float hi) {
    ull d;
    asm("mov.b64 %0, {%1, %2};" : "=l"(d) : "f"(lo), "f"(hi));
    return d;
}
__device__ __forceinline__ void unpack2(ull v, float& lo, float& hi) {
    asm("mov.b64 {%0, %1}, %2;" : "=f"(lo), "=f"(hi) : "l"(v));
}
__device__ __forceinline__ uint32_t smem_u32(const void* p) {
    uint32_t a;
    asm("{ .reg .u64 t; cvta.to.shared.u64 t, %1; cvt.u32.u64 %0, t; }" : "=r"(a) : "l"(p));
    return a;
}
#define CP_ASYNC16(dst, src) \
    asm volatile("cp.async.cg.shared.global [%0], [%1], 16;" :: "r"(dst), "l"(src))
#define CP_COMMIT() asm volatile("cp.async.commit_group;" ::: "memory")
#define CP_WAIT0()  asm volatile("cp.async.wait_group 0;" ::: "memory")

// ---------------- kernel 0a: row sums ---------------------------------------
__global__ void rowstat_kernel(const float* __restrict__ E)
{
    int i = blockIdx.x;
    int t = threadIdx.x;            // 128 threads
    float v = E[(size_t)i * DD + t];
    float s = v, q = v * v;
    #pragma unroll
    for (int o = 16; o; o >>= 1) {
        s += __shfl_down_sync(0xffffffffu, s, o);
        q += __shfl_down_sync(0xffffffffu, q, o);
    }
    __shared__ float ss[4], qq[4];
    if ((t & 31) == 0) { ss[t >> 5] = s; qq[t >> 5] = q; }
    __syncthreads();
    if (t == 0) {
        g_s[i]  = ss[0] + ss[1] + ss[2] + ss[3];
        g_sq[i] = qq[0] + qq[1] + qq[2] + qq[3];
    }
}

// ---------------- kernel 0b: tiled transpose E -> E_T ------------------------
__global__ void transpose_kernel(const float* __restrict__ E)
{
    __shared__ float t[32][33];
    const int tx = threadIdx.x & 31, ty = threadIdx.x >> 5;   // 32x8
    const int i0 = blockIdx.x * 32, k0 = blockIdx.y * 32;
    #pragma unroll
    for (int p = 0; p < 4; p++)
        t[ty + 8 * p][tx] = E[(size_t)(i0 + ty + 8 * p) * DD + k0 + tx];
    __syncthreads();
    #pragma unroll
    for (int p = 0; p < 4; p++)
        g_ET[(size_t)(k0 + ty + 8 * p) * BN + i0 + tx] = t[tx][ty + 8 * p];
}

// ---------------- kernel 1: ballot-pack + smem permute of masks -------------
__global__ __launch_bounds__(256)
void mask_kernel(const int* __restrict__ tgt,
                 const unsigned* __restrict__ P,
                 const unsigned* __restrict__ N)
{
    __shared__ int sTgt[BN];                 // 16 KB
    __shared__ unsigned sP[NWORDS], sN[NWORDS];

    const int tid = threadIdx.x;
    const int lane = tid & 31, warp = tid >> 5;

    for (int m = tid; m < BN; m += 256) sTgt[m] = tgt[m];

    for (int r = 0; r < RPB; r++) {
        const int i = blockIdx.x * RPB + r;
        __syncthreads();

        for (int c = warp; c < NWORDS; c += 8) {
            unsigned pv = P[(size_t)i * BN + c * 32 + lane];
            unsigned nv = N[(size_t)i * BN + c * 32 + lane];
            unsigned pb = __ballot_sync(0xffffffffu, pv != 0u);
            unsigned nb = __ballot_sync(0xffffffffu, nv != 0u);
            if (lane == 0) { sP[c] = pb; sN[c] = nb; }
        }
        __syncthreads();

        const int wd = tid & 127;
        const unsigned* src = (tid < 128) ? sP : sN;
        unsigned out = 0u;
        #pragma unroll
        for (int u = 0; u < 32; u++) {
            int b  = (u + wd) & 31;
            int tj = sTgt[wd * 32 + b];
            out |= ((src[tj >> 5] >> (tj & 31)) & 1u) << b;
        }
        if (tid < 128) g_posbits[i * NWORDS + wd] = out;
        else           g_negbits[i * NWORDS + wd] = out;
    }
}

// ---------------- kernel 2: symmetric SGEMM (f32x2, cp.async) + epilogue ----
__device__ __forceinline__ int tri_off(int k) { return k * 32 - (k * (k - 1)) / 2; }

__global__ __launch_bounds__(256, 2)
void main_kernel()
{
    extern __shared__ __align__(16) char dsm[];
    // per-point distance constants
    __shared__ float aRow[128], aCol[128], bRow[128], bCol[128];
    __shared__ unsigned smPos[128][4], smNeg[128][4];    // i-rows @ j-range
    __shared__ unsigned smPos2[128][4], smNeg2[128][4];  // j-rows @ i-range

    const int tid = threadIdx.x;
    const int lane = tid & 31;
    const int tx = tid & 15;        // j direction
    const int ty = tid >> 4;        // i direction
    const uint32_t dbase = smem_u32(dsm);

    // triangular decode: block t -> (bi, bj), bi <= bj
    const int tblk = blockIdx.x;
    int bi = (int)floorf((65.0f - sqrtf(4225.0f - 8.0f * (float)tblk)) * 0.5f);
    if (bi < 0) bi = 0; if (bi > 31) bi = 31;
    while (tri_off(bi + 1) <= tblk) bi++;
    while (tri_off(bi) > tblk) bi--;
    const int bj = bi + (tblk - tri_off(bi));
    const int i0 = bi * 128;
    const int j0 = bj * 128;
    const bool diag = (bi == bj);

    const float deps = (float)DD * (EPSF * EPSF);
    if (tid < 128) {
        float sqi = g_sq[i0 + tid], si = g_s[i0 + tid];
        float sqj = g_sq[j0 + tid], sj = g_s[j0 + tid];
        aRow[tid] = sqi + 2.0f * EPSF * si;
        aCol[tid] = sqi - 2.0f * EPSF * si + deps;
        bRow[tid] = sqj + 2.0f * EPSF * sj;
        bCol[tid] = sqj - 2.0f * EPSF * sj + deps;
    }
    for (int m = tid; m < 512; m += 256) {
        int r = m >> 2, w = m & 3;
        smPos [r][w] = g_posbits[(i0 + r) * NWORDS + (j0 >> 5) + w];
        smNeg [r][w] = g_negbits[(i0 + r) * NWORDS + (j0 >> 5) + w];
        smPos2[r][w] = g_posbits[(j0 + r) * NWORDS + (i0 >> 5) + w];
        smNeg2[r][w] = g_negbits[(j0 + r) * NWORDS + (i0 >> 5) + w];
    }

    // ---- cp.async stage of chunk `kk` into buffer `b` -----------------------
    // A slice rows i0.., B slice rows j0..; E_T row k holds BN floats.
    auto issue_chunk = [&](int kk, int b) {
        const uint32_t bufA = dbase + b * BUFB;
        const uint32_t bufB = bufA + CHUNKF;
        #pragma unroll
        for (int it = 0; it < 4; it++) {
            int g = tid + it * 256;          // 0..1023
            int k = g >> 5, c = g & 31;      // k-row, 16B chunk
            const float* srcA = g_ET + (size_t)(kk + k) * BN + i0 + c * 4;
            const float* srcB = g_ET + (size_t)(kk + k) * BN + j0 + c * 4;
            CP_ASYNC16(bufA + (k * LDA + c * 4) * 4, srcA);
            CP_ASYNC16(bufB + (k * LDA + c * 4) * 4, srcB);
        }
        CP_COMMIT();
    };

    ull acc2[8][4];
    #pragma unroll
    for (int r = 0; r < 8; r++)
        #pragma unroll
        for (int c = 0; c < 4; c++) acc2[r][c] = 0ull;

    issue_chunk(0, 0);

    #pragma unroll
    for (int kk = 0; kk < 4; kk++) {
        CP_WAIT0();
        __syncthreads();
        if (kk < 3) issue_chunk((kk + 1) * TK, (kk + 1) & 1);

        const float* As = (const float*)(dsm + (kk & 1) * BUFB);
        const float* Bs = As + CHUNKF / 4;
        #pragma unroll
        for (int k = 0; k < TK; k++) {
            float4 a0 = *(const float4*)(As + k * LDA + ty * 8);
            float4 a1 = *(const float4*)(As + k * LDA + ty * 8 + 4);
            const ull* bp = (const ull*)(Bs + k * LDA + tx * 8);
            ull b2[4] = { bp[0], bp[1], bp[2], bp[3] };
            ull a2[8] = { pack2(a0.x, a0.x), pack2(a0.y, a0.y),
                          pack2(a0.z, a0.z), pack2(a0.w, a0.w),
                          pack2(a1.x, a1.x), pack2(a1.y, a1.y),
                          pack2(a1.z, a1.z), pack2(a1.w, a1.w) };
            #pragma unroll
            for (int r = 0; r < 8; r++)
                #pragma unroll
                for (int c = 0; c < 4; c++)
                    acc2[r][c] = fma2(a2[r], b2[c], acc2[r][c]);
        }
    }

    // unpack accumulators
    float acc[8][8];
    #pragma unroll
    for (int r = 0; r < 8; r++)
        #pragma unroll
        for (int c = 0; c < 4; c++)
            unpack2(acc2[r][c], acc[r][2 * c], acc[r][2 * c + 1]);

    // ---- row-side epilogue: keys = clamped d^2 bits (sqrt-free) ------------
    // partners for fixed row = 16 lanes of same half-warp -> shfl width 16
    float cj[8];
    #pragma unroll
    for (int c = 0; c < 8; c++) cj[c] = bCol[tx * 8 + c];

    #pragma unroll
    for (int r = 0; r < 8; r++) {
        int li = ty * 8 + r;
        float base = aRow[li];
        unsigned pw = smPos[li][tx >> 2];
        unsigned nw = smNeg[li][tx >> 2];
        ull bp = 0ull, bn = 0xFFFFFFFFFFFFFFFFull;
        #pragma unroll
        for (int c = 0; c < 8; c++) {
            int jl = tx * 8 + c;
            float d2 = fmaf(acc[r][c], -2.0f, base + cj[c]);
            unsigned bits = __float_as_uint(fmaxf(d2, 0.0f));
            unsigned j = (unsigned)(j0 + jl);
            if ((pw >> (jl & 31)) & 1u) {
                ull pk = ((ull)bits << 32) | (~j);
                if (pk > bp) bp = pk;               // ties: smaller j wins
            }
            if ((nw >> (jl & 31)) & 1u) {
                ull pk = ((ull)bits << 32) | j;
                if (pk < bn) bn = pk;
            }
        }
        #pragma unroll
        for (int o = 8; o; o >>= 1) {
            ull a = __shfl_down_sync(0xffffffffu, bp, o, 16); if (a > bp) bp = a;
            ull b = __shfl_down_sync(0xffffffffu, bn, o, 16); if (b < bn) bn = b;
        }
        if ((lane & 15) == 0) {
            g_posPart[(size_t)(i0 + li) * PART + bj] = bp;
            g_negPart[(size_t)(i0 + li) * PART + bj] = bn;
        }
    }

    // ---- col-side epilogue (off-diag): rows j over cols i ------------------
    if (!diag) {
        ull (*stP)[16] = (ull (*)[16])dsm;              // reuse buf0 (16 KB)
        ull (*stN)[16] = (ull (*)[16])(dsm + 16384);
        float ci[8];
        #pragma unroll
        for (int r = 0; r < 8; r++) ci[r] = aCol[ty * 8 + r];

        #pragma unroll
        for (int c = 0; c < 8; c++) {
            int jl = tx * 8 + c;
            float base = bRow[jl];
            unsigned pw = smPos2[jl][ty >> 2];
            unsigned nw = smNeg2[jl][ty >> 2];
            ull bp = 0ull, bn = 0xFFFFFFFFFFFFFFFFull;
            #pragma unroll
            for (int r = 0; r < 8; r++) {
                int il = ty * 8 + r;
                float d2 = fmaf(acc[r][c], -2.0f, base + ci[r]);
                unsigned bits = __float_as_uint(fmaxf(d2, 0.0f));
                unsigned jx = (unsigned)(i0 + il);      // candidate col = i
                if ((pw >> (il & 31)) & 1u) {
                    ull pk = ((ull)bits << 32) | (~jx);
                    if (pk > bp) bp = pk;
                }
                if ((nw >> (il & 31)) & 1u) {
                    ull pk = ((ull)bits << 32) | jx;
                    if (pk < bn) bn = pk;
                }
            }
            stP[jl][ty] = bp;
            stN[jl][ty] = bn;
        }
        __syncthreads();
        int jl = tid & 127;
        if (tid < 128) {
            ull m = 0ull;
            #pragma unroll
            for (int k = 0; k < 16; k++) {
                ull v = stP[jl][(jl + k) & 15]; if (v > m) m = v;
            }
            g_posPart[(size_t)(j0 + jl) * PART + bi] = m;
        } else {
            ull m = 0xFFFFFFFFFFFFFFFFull;
            #pragma unroll
            for (int k = 0; k < 16; k++) {
                ull v = stN[jl][(jl + k) & 15]; if (v < m) m = v;
            }
            g_negPart[(size_t)(j0 + jl) * PART + bi] = m;
        }
    }
}

// ---------------- kernel 3: per-row reduce + exact triplet loss ------------
__global__ void row_kernel(const float* __restrict__ E)
{
    int i = blockIdx.x;
    int t = threadIdx.x;            // 128 threads

    ull bp = 0ull, bn = 0xFFFFFFFFFFFFFFFFull;
    if (t < PART) {
        bp = g_posPart[(size_t)i * PART + t];
        bn = g_negPart[(size_t)i * PART + t];
    }
    #pragma unroll
    for (int o = 16; o; o >>= 1) {
        ull a = __shfl_down_sync(0xffffffffu, bp, o); if (a > bp) bp = a;
        ull b = __shfl_down_sync(0xffffffffu, bn, o); if (b < bn) bn = b;
    }
    __shared__ ull shP, shN;
    if (t == 0) { shP = bp; shN = bn; }
    __syncthreads();
    bp = shP; bn = shN;

    if (bp == 0ull || bn == 0xFFFFFFFFFFFFFFFFull) {   // invalid row
        if (t == 0) { g_loss[i] = 0.0f; g_w[i] = 0.0f; }
        return;
    }
    int pi = (int)(~(unsigned)bp) & (BN - 1);   // undo ~j
    int ni = (int)((unsigned)bn);

    float av = E[(size_t)i  * DD + t];
    float pv = E[(size_t)pi * DD + t];
    float nv = E[(size_t)ni * DD + t];
    float d1 = av - pv + EPSF;
    float d2 = av - nv + EPSF;
    float d3 = pv - nv + EPSF;
    float s1 = d1 * d1, s2 = d2 * d2, s3 = d3 * d3;
    #pragma unroll
    for (int o = 16; o; o >>= 1) {
        s1 += __shfl_down_sync(0xffffffffu, s1, o);
        s2 += __shfl_down_sync(0xffffffffu, s2, o);
        s3 += __shfl_down_sync(0xffffffffu, s3, o);
    }
    __shared__ float r1[4], r2[4], r3[4];
    if ((t & 31) == 0) { r1[t >> 5] = s1; r2[t >> 5] = s2; r3[t >> 5] = s3; }
    __syncthreads();
    if (t == 0) {
        float S1 = r1[0] + r1[1] + r1[2] + r1[3];
        float S2 = r2[0] + r2[1] + r2[2] + r2[3];
        float S3 = r3[0] + r3[1] + r3[2] + r3[3];
        float ap = sqrtf(S1), an = sqrtf(S2), pn = sqrtf(S3);
        float loss = fmaxf(ap - fminf(an, pn) + 1.0f, 0.0f);
        g_loss[i] = loss;
        g_w[i] = 1.0f;
    }
}

// ---------------- kernel 4: deterministic scalar reduction -----------------
__global__ void final_kernel(float* __restrict__ out)
{
    int t = threadIdx.x;            // 1024 threads
    float ls = 0.0f, ws = 0.0f;
    for (int r = t; r < BN; r += 1024) { ls += g_loss[r]; ws += g_w[r]; }
    #pragma unroll
    for (int o = 16; o; o >>= 1) {
        ls += __shfl_down_sync(0xffffffffu, ls, o);
        ws += __shfl_down_sync(0xffffffffu, ws, o);
    }
    __shared__ float sl[32], sw[32];
    if ((t & 31) == 0) { sl[t >> 5] = ls; sw[t >> 5] = ws; }
    __syncthreads();
    if (t == 0) {
        float L = 0.0f, W = 0.0f;
        for (int w = 0; w < 32; w++) { L += sl[w]; W += sw[w]; }
        out[0] = L / fmaxf(W, 1.0f);
    }
}

// ---------------- launch ----------------------------------------------------
extern "C" void kernel_launch(void* const* d_in, const int* in_sizes, int n_in,
                              void* d_out, int out_size)
{
    const float*    E   = (const float*)d_in[0];
    const int*      tgt = (const int*)d_in[1];
    const unsigned* P   = (const unsigned*)d_in[2];
    const unsigned* N   = (const unsigned*)d_in[3];
    float* out = (float*)d_out;

    static int configured = 0;
    if (!configured) {
        cudaFuncSetAttribute(main_kernel,
                             cudaFuncAttributeMaxDynamicSharedMemorySize, DSMEM);
        configured = 1;
    }

    rowstat_kernel<<<BN, 128>>>(E);
    {
        dim3 tg(BN / 32, DD / 32);
        transpose_kernel<<<tg, 256>>>(E);
    }
    mask_kernel<<<BN / RPB, 256>>>(tgt, P, N);
    main_kernel<<<NBLK, 256, DSMEM>>>();
    row_kernel<<<BN, 128>>>(E);
    final_kernel<<<1, 1024>>>(out);
}

// round 16
// speedup vs baseline: 2.5372x; 1.1460x over previous
#include <cuda_runtime.h>
#include <stdint.h>

#define BN 4096
#define DD 128
#define EPSF 1e-6f
#define NWORDS (BN/32)        // 128 words per row
#define PART 32               // one reduced slot per "other tile" per row
#define TK 32                 // K chunk
#define NT 32                 // 32 row/col tiles
#define NBLK 528              // NT*(NT+1)/2 upper-triangular blocks
#define RPB 8                 // rows per block in mask kernel
#define LDA 132               // padded smem row (floats)
#define CHUNKF (TK * LDA * 4) // 16896 B: one matrix chunk
#define BUFB (2 * CHUNKF)     // A+B for one stage
#define DSMEM (2 * BUFB)      // double buffered: 67584 B

// ---------------- device scratch (static; no allocations allowed) ----------
__device__ float g_ET[DD * BN];          // transposed embedding [k][i]
__device__ float g_sq[BN];
__device__ float g_s[BN];
__device__ unsigned g_posbits[BN * NWORDS];
__device__ unsigned g_negbits[BN * NWORDS];
__device__ unsigned long long g_posPart[(size_t)BN * PART];
__device__ unsigned long long g_negPart[(size_t)BN * PART];
__device__ float g_loss[BN];
__device__ float g_w[BN];

// ---------------- helpers ----------------------------------------------------
typedef unsigned long long ull;
__device__ __forceinline__ ull fma2(ull a, ull b, ull c) {
    ull d;
    asm("fma.rn.f32x2 %0, %1, %2, %3;" : "=l"(d) : "l"(a), "l"(b), "l"(c));
    return d;
}
__device__ __forceinline__ ull pack2(float lo, float hi) {
    ull d;
    asm("mov.b64 %0, {%1, %2};" : "=l"(d) : "f"(lo), "f"(hi));
    return d;
}
__device__ __forceinline__ void unpack2(ull v, float& lo, float& hi) {
    asm("mov.b64 {%0, %1}, %2;" : "=f"(lo), "=f"(hi) : "l"(v));
}
__device__ __forceinline__ uint32_t smem_u32(const void* p) {
    uint32_t a;
    asm("{ .reg .u64 t; cvta.to.shared.u64 t, %1; cvt.u32.u64 %0, t; }" : "=r"(a) : "l"(p));
    return a;
}
#define CP_ASYNC16(dst, src) \
    asm volatile("cp.async.cg.shared.global [%0], [%1], 16;" :: "r"(dst), "l"(src))
#define CP_COMMIT() asm volatile("cp.async.commit_group;" ::: "memory")
#define CP_WAIT0()  asm volatile("cp.async.wait_group 0;" ::: "memory")

// ---------------- kernel 0: tiled transpose E -> E_T -------------------------
__global__ void transpose_kernel(const float* __restrict__ E)
{
    __shared__ float t[32][33];
    const int tx = threadIdx.x & 31, ty = threadIdx.x >> 5;   // 32x8
    const int i0 = blockIdx.x * 32, k0 = blockIdx.y * 32;
    #pragma unroll
    for (int p = 0; p < 4; p++)
        t[ty + 8 * p][tx] = E[(size_t)(i0 + ty + 8 * p) * DD + k0 + tx];
    __syncthreads();
    #pragma unroll
    for (int p = 0; p < 4; p++)
        g_ET[(size_t)(k0 + ty + 8 * p) * BN + i0 + tx] = t[tx][ty + 8 * p];
}

// ---------------- kernel 1: rowstat + MLP ballot-pack + smem permute --------
// Masks are 4-byte bool elements; nonzero <=> true.
__global__ __launch_bounds__(256)
void mask_kernel(const float* __restrict__ E,
                 const int* __restrict__ tgt,
                 const unsigned* __restrict__ P,
                 const unsigned* __restrict__ N)
{
    __shared__ int sTgt[BN];                       // 16 KB
    __shared__ unsigned sP[RPB][NWORDS], sN[RPB][NWORDS];   // 8 KB

    const int tid = threadIdx.x;
    const int lane = tid & 31, warp = tid >> 5;
    const int i0 = blockIdx.x * RPB;

    for (int m = tid; m < BN; m += 256) sTgt[m] = tgt[m];

    // rowstat: warp w reduces row i0+w (one float4 per lane)
    {
        const float4 v = ((const float4*)(E + (size_t)(i0 + warp) * DD))[lane];
        float s = v.x + v.y + v.z + v.w;
        float q = v.x * v.x + v.y * v.y + v.z * v.z + v.w * v.w;
        #pragma unroll
        for (int o = 16; o; o >>= 1) {
            s += __shfl_down_sync(0xffffffffu, s, o);
            q += __shfl_down_sync(0xffffffffu, q, o);
        }
        if (lane == 0) { g_s[i0 + warp] = s; g_sq[i0 + warp] = q; }
    }

    // ballot-pack all 8 rows; loads batched ahead of ballots (MLP ~32)
    for (int r = 0; r < RPB; r++) {
        const unsigned* Pr = P + (size_t)(i0 + r) * BN;
        const unsigned* Nr = N + (size_t)(i0 + r) * BN;
        unsigned pv[16], nv[16];
        #pragma unroll
        for (int c = 0; c < 16; c++) {
            int col = (c * 8 + warp) * 32 + lane;
            pv[c] = Pr[col];
            nv[c] = Nr[col];
        }
        #pragma unroll
        for (int c = 0; c < 16; c++) {
            unsigned pb = __ballot_sync(0xffffffffu, pv[c] != 0u);
            unsigned nb = __ballot_sync(0xffffffffu, nv[c] != 0u);
            if (lane == 0) { sP[r][c * 8 + warp] = pb; sN[r][c * 8 + warp] = nb; }
        }
    }
    __syncthreads();

    // permute: 2048 tasks (8 rows x 128 words x pos/neg)
    // staggered bit order (b = (u+wd)&31) -> conflict-free sTgt LDS
    #pragma unroll
    for (int t = 0; t < 8; t++) {
        const int rr = t;
        const int half = (tid >> 7) & 1;          // 0 pos, 1 neg
        const int wd = tid & 127;
        const unsigned* src = half ? sN[rr] : sP[rr];
        unsigned out = 0u;
        #pragma unroll
        for (int u = 0; u < 32; u++) {
            int b  = (u + wd) & 31;
            int tj = sTgt[wd * 32 + b];
            out |= ((src[tj >> 5] >> (tj & 31)) & 1u) << b;
        }
        if (half == 0) g_posbits[(i0 + rr) * NWORDS + wd] = out;
        else           g_negbits[(i0 + rr) * NWORDS + wd] = out;
    }
}

// ---------------- kernel 2: symmetric SGEMM (f32x2, cp.async) + epilogue ----
__device__ __forceinline__ int tri_off(int k) { return k * 32 - (k * (k - 1)) / 2; }

__global__ __launch_bounds__(256, 2)
void main_kernel()
{
    extern __shared__ __align__(16) char dsm[];
    // per-point distance constants
    __shared__ float aRow[128], aCol[128], bRow[128], bCol[128];
    __shared__ unsigned smPos[128][4], smNeg[128][4];    // i-rows @ j-range
    __shared__ unsigned smPos2[128][4], smNeg2[128][4];  // j-rows @ i-range

    const int tid = threadIdx.x;
    const int lane = tid & 31;
    const int tx = tid & 15;        // j direction
    const int ty = tid >> 4;        // i direction
    const uint32_t dbase = smem_u32(dsm);

    // triangular decode: block t -> (bi, bj), bi <= bj
    const int tblk = blockIdx.x;
    int bi = (int)floorf((65.0f - sqrtf(4225.0f - 8.0f * (float)tblk)) * 0.5f);
    if (bi < 0) bi = 0; if (bi > 31) bi = 31;
    while (tri_off(bi + 1) <= tblk) bi++;
    while (tri_off(bi) > tblk) bi--;
    const int bj = bi + (tblk - tri_off(bi));
    const int i0 = bi * 128;
    const int j0 = bj * 128;
    const bool diag = (bi == bj);

    const float deps = (float)DD * (EPSF * EPSF);
    if (tid < 128) {
        float sqi = g_sq[i0 + tid], si = g_s[i0 + tid];
        float sqj = g_sq[j0 + tid], sj = g_s[j0 + tid];
        aRow[tid] = sqi + 2.0f * EPSF * si;
        aCol[tid] = sqi - 2.0f * EPSF * si + deps;
        bRow[tid] = sqj + 2.0f * EPSF * sj;
        bCol[tid] = sqj - 2.0f * EPSF * sj + deps;
    }
    for (int m = tid; m < 512; m += 256) {
        int r = m >> 2, w = m & 3;
        smPos [r][w] = g_posbits[(i0 + r) * NWORDS + (j0 >> 5) + w];
        smNeg [r][w] = g_negbits[(i0 + r) * NWORDS + (j0 >> 5) + w];
        smPos2[r][w] = g_posbits[(j0 + r) * NWORDS + (i0 >> 5) + w];
        smNeg2[r][w] = g_negbits[(j0 + r) * NWORDS + (i0 >> 5) + w];
    }

    // ---- cp.async stage of chunk `kk` into buffer `b` -----------------------
    auto issue_chunk = [&](int kk, int b) {
        const uint32_t bufA = dbase + b * BUFB;
        const uint32_t bufB = bufA + CHUNKF;
        #pragma unroll
        for (int it = 0; it < 4; it++) {
            int g = tid + it * 256;          // 0..1023
            int k = g >> 5, c = g & 31;      // k-row, 16B chunk
            const float* srcA = g_ET + (size_t)(kk + k) * BN + i0 + c * 4;
            const float* srcB = g_ET + (size_t)(kk + k) * BN + j0 + c * 4;
            CP_ASYNC16(bufA + (k * LDA + c * 4) * 4, srcA);
            CP_ASYNC16(bufB + (k * LDA + c * 4) * 4, srcB);
        }
        CP_COMMIT();
    };

    ull acc2[8][4];
    #pragma unroll
    for (int r = 0; r < 8; r++)
        #pragma unroll
        for (int c = 0; c < 4; c++) acc2[r][c] = 0ull;

    issue_chunk(0, 0);

    #pragma unroll
    for (int kk = 0; kk < 4; kk++) {
        CP_WAIT0();
        __syncthreads();
        if (kk < 3) issue_chunk((kk + 1) * TK, (kk + 1) & 1);

        const float* As = (const float*)(dsm + (kk & 1) * BUFB);
        const float* Bs = As + CHUNKF / 4;
        #pragma unroll
        for (int k = 0; k < TK; k++) {
            float4 a0 = *(const float4*)(As + k * LDA + ty * 8);
            float4 a1 = *(const float4*)(As + k * LDA + ty * 8 + 4);
            const ull* bp = (const ull*)(Bs + k * LDA + tx * 8);
            ull b2[4] = { bp[0], bp[1], bp[2], bp[3] };
            ull a2[8] = { pack2(a0.x, a0.x), pack2(a0.y, a0.y),
                          pack2(a0.z, a0.z), pack2(a0.w, a0.w),
                          pack2(a1.x, a1.x), pack2(a1.y, a1.y),
                          pack2(a1.z, a1.z), pack2(a1.w, a1.w) };
            #pragma unroll
            for (int r = 0; r < 8; r++)
                #pragma unroll
                for (int c = 0; c < 4; c++)
                    acc2[r][c] = fma2(a2[r], b2[c], acc2[r][c]);
        }
    }

    // unpack accumulators
    float acc[8][8];
    #pragma unroll
    for (int r = 0; r < 8; r++)
        #pragma unroll
        for (int c = 0; c < 4; c++)
            unpack2(acc2[r][c], acc[r][2 * c], acc[r][2 * c + 1]);

    // ---- row-side epilogue: keys = clamped d^2 bits (sqrt-free) ------------
    float cj[8];
    #pragma unroll
    for (int c = 0; c < 8; c++) cj[c] = bCol[tx * 8 + c];

    #pragma unroll
    for (int r = 0; r < 8; r++) {
        int li = ty * 8 + r;
        float base = aRow[li];
        unsigned pw = smPos[li][tx >> 2];
        unsigned nw = smNeg[li][tx >> 2];
        ull bp = 0ull, bn = 0xFFFFFFFFFFFFFFFFull;
        #pragma unroll
        for (int c = 0; c < 8; c++) {
            int jl = tx * 8 + c;
            float d2 = fmaf(acc[r][c], -2.0f, base + cj[c]);
            unsigned bits = __float_as_uint(fmaxf(d2, 0.0f));
            unsigned j = (unsigned)(j0 + jl);
            if ((pw >> (jl & 31)) & 1u) {
                ull pk = ((ull)bits << 32) | (~j);
                if (pk > bp) bp = pk;               // ties: smaller j wins
            }
            if ((nw >> (jl & 31)) & 1u) {
                ull pk = ((ull)bits << 32) | j;
                if (pk < bn) bn = pk;
            }
        }
        #pragma unroll
        for (int o = 8; o; o >>= 1) {
            ull a = __shfl_down_sync(0xffffffffu, bp, o, 16); if (a > bp) bp = a;
            ull b = __shfl_down_sync(0xffffffffu, bn, o, 16); if (b < bn) bn = b;
        }
        if ((lane & 15) == 0) {
            g_posPart[(size_t)(i0 + li) * PART + bj] = bp;
            g_negPart[(size_t)(i0 + li) * PART + bj] = bn;
        }
    }

    // ---- col-side epilogue (off-diag): rows j over cols i ------------------
    if (!diag) {
        ull (*stP)[16] = (ull (*)[16])dsm;              // reuse buf0 (16 KB)
        ull (*stN)[16] = (ull (*)[16])(dsm + 16384);
        float ci[8];
        #pragma unroll
        for (int r = 0; r < 8; r++) ci[r] = aCol[ty * 8 + r];

        #pragma unroll
        for (int c = 0; c < 8; c++) {
            int jl = tx * 8 + c;
            float base = bRow[jl];
            unsigned pw = smPos2[jl][ty >> 2];
            unsigned nw = smNeg2[jl][ty >> 2];
            ull bp = 0ull, bn = 0xFFFFFFFFFFFFFFFFull;
            #pragma unroll
            for (int r = 0; r < 8; r++) {
                int il = ty * 8 + r;
                float d2 = fmaf(acc[r][c], -2.0f, base + ci[r]);
                unsigned bits = __float_as_uint(fmaxf(d2, 0.0f));
                unsigned jx = (unsigned)(i0 + il);      // candidate col = i
                if ((pw >> (il & 31)) & 1u) {
                    ull pk = ((ull)bits << 32) | (~jx);
                    if (pk > bp) bp = pk;
                }
                if ((nw >> (il & 31)) & 1u) {
                    ull pk = ((ull)bits << 32) | jx;
                    if (pk < bn) bn = pk;
                }
            }
            stP[jl][ty] = bp;
            stN[jl][ty] = bn;
        }
        __syncthreads();
        int jl = tid & 127;
        if (tid < 128) {
            ull m = 0ull;
            #pragma unroll
            for (int k = 0; k < 16; k++) {
                ull v = stP[jl][(jl + k) & 15]; if (v > m) m = v;
            }
            g_posPart[(size_t)(j0 + jl) * PART + bi] = m;
        } else {
            ull m = 0xFFFFFFFFFFFFFFFFull;
            #pragma unroll
            for (int k = 0; k < 16; k++) {
                ull v = stN[jl][(jl + k) & 15]; if (v < m) m = v;
            }
            g_negPart[(size_t)(j0 + jl) * PART + bi] = m;
        }
    }
}

// ---------------- kernel 3: per-row reduce + exact triplet loss ------------
__global__ void row_kernel(const float* __restrict__ E)
{
    int i = blockIdx.x;
    int t = threadIdx.x;            // 128 threads

    ull bp = 0ull, bn = 0xFFFFFFFFFFFFFFFFull;
    if (t < PART) {
        bp = g_posPart[(size_t)i * PART + t];
        bn = g_negPart[(size_t)i * PART + t];
    }
    #pragma unroll
    for (int o = 16; o; o >>= 1) {
        ull a = __shfl_down_sync(0xffffffffu, bp, o); if (a > bp) bp = a;
        ull b = __shfl_down_sync(0xffffffffu, bn, o); if (b < bn) bn = b;
    }
    __shared__ ull shP, shN;
    if (t == 0) { shP = bp; shN = bn; }
    __syncthreads();
    bp = shP; bn = shN;

    if (bp == 0ull || bn == 0xFFFFFFFFFFFFFFFFull) {   // invalid row
        if (t == 0) { g_loss[i] = 0.0f; g_w[i] = 0.0f; }
        return;
    }
    int pi = (int)(~(unsigned)bp) & (BN - 1);   // undo ~j
    int ni = (int)((unsigned)bn);

    float av = E[(size_t)i  * DD + t];
    float pv = E[(size_t)pi * DD + t];
    float nv = E[(size_t)ni * DD + t];
    float d1 = av - pv + EPSF;
    float d2 = av - nv + EPSF;
    float d3 = pv - nv + EPSF;
    float s1 = d1 * d1, s2 = d2 * d2, s3 = d3 * d3;
    #pragma unroll
    for (int o = 16; o; o >>= 1) {
        s1 += __shfl_down_sync(0xffffffffu, s1, o);
        s2 += __shfl_down_sync(0xffffffffu, s2, o);
        s3 += __shfl_down_sync(0xffffffffu, s3, o);
    }
    __shared__ float r1[4], r2[4], r3[4];
    if ((t & 31) == 0) { r1[t >> 5] = s1; r2[t >> 5] = s2; r3[t >> 5] = s3; }
    __syncthreads();
    if (t == 0) {
        float S1 = r1[0] + r1[1] + r1[2] + r1[3];
        float S2 = r2[0] + r2[1] + r2[2] + r2[3];
        float S3 = r3[0] + r3[1] + r3[2] + r3[3];
        float ap = sqrtf(S1), an = sqrtf(S2), pn = sqrtf(S3);
        float loss = fmaxf(ap - fminf(an, pn) + 1.0f, 0.0f);
        g_loss[i] = loss;
        g_w[i] = 1.0f;
    }
}

// ---------------- kernel 4: deterministic scalar reduction -----------------
__global__ void final_kernel(float* __restrict__ out)
{
    int t = threadIdx.x;            // 1024 threads
    float ls = 0.0f, ws = 0.0f;
    for (int r = t; r < BN; r += 1024) { ls += g_loss[r]; ws += g_w[r]; }
    #pragma unroll
    for (int o = 16; o; o >>= 1) {
        ls += __shfl_down_sync(0xffffffffu, ls, o);
        ws += __shfl_down_sync(0xffffffffu, ws, o);
    }
    __shared__ float sl[32], sw[32];
    if ((t & 31) == 0) { sl[t >> 5] = ls; sw[t >> 5] = ws; }
    __syncthreads();
    if (t == 0) {
        float L = 0.0f, W = 0.0f;
        for (int w = 0; w < 32; w++) { L += sl[w]; W += sw[w]; }
        out[0] = L / fmaxf(W, 1.0f);
    }
}

// ---------------- launch ----------------------------------------------------
extern "C" void kernel_launch(void* const* d_in, const int* in_sizes, int n_in,
                              void* d_out, int out_size)
{
    const float*    E   = (const float*)d_in[0];
    const int*      tgt = (const int*)d_in[1];
    const unsigned* P   = (const unsigned*)d_in[2];
    const unsigned* N   = (const unsigned*)d_in[3];
    float* out = (float*)d_out;

    static int configured = 0;
    if (!configured) {
        cudaFuncSetAttribute(main_kernel,
                             cudaFuncAttributeMaxDynamicSharedMemorySize, DSMEM);
        configured = 1;
    }

    {
        dim3 tg(BN / 32, DD / 32);
        transpose_kernel<<<tg, 256>>>(E);
    }
    mask_kernel<<<BN / RPB, 256>>>(E, tgt, P, N);
    main_kernel<<<NBLK, 256, DSMEM>>>();
    row_kernel<<<BN, 128>>>(E);
    final_kernel<<<1, 1024>>>(out);
}

// round 17
// speedup vs baseline: 2.6580x; 1.0476x over previous
#include <cuda_runtime.h>
#include <stdint.h>

#define BN 4096
#define DD 128
#define EPSF 1e-6f
#define NWORDS (BN/32)        // 128 words per row
#define PART 32               // one reduced slot per "other tile" per row
#define TK 32                 // K chunk
#define NT 32                 // 32 row/col tiles
#define NBLK 528              // NT*(NT+1)/2 upper-triangular blocks
#define RPB 8                 // rows per block in mask kernel
#define LDA 132               // padded smem row (floats)
#define CHUNKF (TK * LDA * 4) // 16896 B: one matrix chunk
#define BUFB (2 * CHUNKF)     // A+B for one stage
#define DSMEM (2 * BUFB)      // double buffered: 67584 B

// ---------------- device scratch (static; no allocations allowed) ----------
__device__ float g_ET[DD * BN];          // transposed embedding [k][i]
__device__ float g_sq[BN];
__device__ float g_s[BN];
__device__ unsigned g_posbits[BN * NWORDS];
__device__ unsigned g_negbits[BN * NWORDS];
__device__ unsigned long long g_posPart[(size_t)BN * PART];
__device__ unsigned long long g_negPart[(size_t)BN * PART];
__device__ float g_loss[BN];
__device__ float g_w[BN];

// ---------------- helpers ----------------------------------------------------
typedef unsigned long long ull;
__device__ __forceinline__ ull fma2(ull a, ull b, ull c) {
    ull d;
    asm("fma.rn.f32x2 %0, %1, %2, %3;" : "=l"(d) : "l"(a), "l"(b), "l"(c));
    return d;
}
__device__ __forceinline__ ull pack2(float lo, float hi) {
    ull d;
    asm("mov.b64 %0, {%1, %2};" : "=l"(d) : "f"(lo), "f"(hi));
    return d;
}
__device__ __forceinline__ void unpack2(ull v, float& lo, float& hi) {
    asm("mov.b64 {%0, %1}, %2;" : "=f"(lo), "=f"(hi) : "l"(v));
}
__device__ __forceinline__ uint32_t smem_u32(const void* p) {
    uint32_t a;
    asm("{ .reg .u64 t; cvta.to.shared.u64 t, %1; cvt.u32.u64 %0, t; }" : "=r"(a) : "l"(p));
    return a;
}
#define CP_ASYNC16(dst, src) \
    asm volatile("cp.async.cg.shared.global [%0], [%1], 16;" :: "r"(dst), "l"(src))
#define CP_COMMIT() asm volatile("cp.async.commit_group;" ::: "memory")
#define CP_WAIT0()  asm volatile("cp.async.wait_group 0;" ::: "memory")

// ---------------- kernel 0: tiled transpose E -> E_T -------------------------
__global__ void transpose_kernel(const float* __restrict__ E)
{
    __shared__ float t[32][33];
    const int tx = threadIdx.x & 31, ty = threadIdx.x >> 5;   // 32x8
    const int i0 = blockIdx.x * 32, k0 = blockIdx.y * 32;
    #pragma unroll
    for (int p = 0; p < 4; p++)
        t[ty + 8 * p][tx] = E[(size_t)(i0 + ty + 8 * p) * DD + k0 + tx];
    __syncthreads();
    #pragma unroll
    for (int p = 0; p < 4; p++)
        g_ET[(size_t)(k0 + ty + 8 * p) * BN + i0 + tx] = t[tx][ty + 8 * p];
}

// ---------------- kernel 1: rowstat + MLP ballot-pack + smem permute --------
__global__ __launch_bounds__(256)
void mask_kernel(const float* __restrict__ E,
                 const int* __restrict__ tgt,
                 const unsigned* __restrict__ P,
                 const unsigned* __restrict__ N)
{
    __shared__ int sTgt[BN];                       // 16 KB
    __shared__ unsigned sP[RPB][NWORDS], sN[RPB][NWORDS];   // 8 KB

    const int tid = threadIdx.x;
    const int lane = tid & 31, warp = tid >> 5;
    const int i0 = blockIdx.x * RPB;

    for (int m = tid; m < BN; m += 256) sTgt[m] = tgt[m];

    // rowstat: warp w reduces row i0+w (one float4 per lane)
    {
        const float4 v = ((const float4*)(E + (size_t)(i0 + warp) * DD))[lane];
        float s = v.x + v.y + v.z + v.w;
        float q = v.x * v.x + v.y * v.y + v.z * v.z + v.w * v.w;
        #pragma unroll
        for (int o = 16; o; o >>= 1) {
            s += __shfl_down_sync(0xffffffffu, s, o);
            q += __shfl_down_sync(0xffffffffu, q, o);
        }
        if (lane == 0) { g_s[i0 + warp] = s; g_sq[i0 + warp] = q; }
    }

    // ballot-pack all 8 rows; loads batched ahead of ballots (MLP ~32)
    for (int r = 0; r < RPB; r++) {
        const unsigned* Pr = P + (size_t)(i0 + r) * BN;
        const unsigned* Nr = N + (size_t)(i0 + r) * BN;
        unsigned pv[16], nv[16];
        #pragma unroll
        for (int c = 0; c < 16; c++) {
            int col = (c * 8 + warp) * 32 + lane;
            pv[c] = Pr[col];
            nv[c] = Nr[col];
        }
        #pragma unroll
        for (int c = 0; c < 16; c++) {
            unsigned pb = __ballot_sync(0xffffffffu, pv[c] != 0u);
            unsigned nb = __ballot_sync(0xffffffffu, nv[c] != 0u);
            if (lane == 0) { sP[r][c * 8 + warp] = pb; sN[r][c * 8 + warp] = nb; }
        }
    }
    __syncthreads();

    // permute: staggered bit order (b = (u+wd)&31) -> conflict-free sTgt LDS
    #pragma unroll
    for (int t = 0; t < 8; t++) {
        const int rr = t;
        const int half = (tid >> 7) & 1;          // 0 pos, 1 neg
        const int wd = tid & 127;
        const unsigned* src = half ? sN[rr] : sP[rr];
        unsigned out = 0u;
        #pragma unroll
        for (int u = 0; u < 32; u++) {
            int b  = (u + wd) & 31;
            int tj = sTgt[wd * 32 + b];
            out |= ((src[tj >> 5] >> (tj & 31)) & 1u) << b;
        }
        if (half == 0) g_posbits[(i0 + rr) * NWORDS + wd] = out;
        else           g_negbits[(i0 + rr) * NWORDS + wd] = out;
    }
}

// ---------------- kernel 2: symmetric SGEMM (f32x2, cp.async) + epilogue ----
// Thread tile remapped to 4+4 split rows/cols for conflict-free B LDS:
// thread (ty,tx) owns rows {ty*4+r, 64+ty*4+r}, cols {tx*4+e, 64+tx*4+e}.
__device__ __forceinline__ int tri_off(int k) { return k * 32 - (k * (k - 1)) / 2; }

__global__ __launch_bounds__(256, 2)
void main_kernel()
{
    extern __shared__ __align__(16) char dsm[];
    __shared__ float aRow[128], aCol[128], bRow[128], bCol[128];
    __shared__ unsigned smPos[128][4], smNeg[128][4];    // i-rows @ j-range
    __shared__ unsigned smPos2[128][4], smNeg2[128][4];  // j-rows @ i-range

    const int tid = threadIdx.x;
    const int lane = tid & 31;
    const int tx = tid & 15;        // j direction
    const int ty = tid >> 4;        // i direction
    const uint32_t dbase = smem_u32(dsm);

    // triangular decode: block t -> (bi, bj), bi <= bj
    const int tblk = blockIdx.x;
    int bi = (int)floorf((65.0f - sqrtf(4225.0f - 8.0f * (float)tblk)) * 0.5f);
    if (bi < 0) bi = 0; if (bi > 31) bi = 31;
    while (tri_off(bi + 1) <= tblk) bi++;
    while (tri_off(bi) > tblk) bi--;
    const int bj = bi + (tblk - tri_off(bi));
    const int i0 = bi * 128;
    const int j0 = bj * 128;
    const bool diag = (bi == bj);

    const float deps = (float)DD * (EPSF * EPSF);
    if (tid < 128) {
        float sqi = g_sq[i0 + tid], si = g_s[i0 + tid];
        float sqj = g_sq[j0 + tid], sj = g_s[j0 + tid];
        aRow[tid] = sqi + 2.0f * EPSF * si;
        aCol[tid] = sqi - 2.0f * EPSF * si + deps;
        bRow[tid] = sqj + 2.0f * EPSF * sj;
        bCol[tid] = sqj - 2.0f * EPSF * sj + deps;
    }
    for (int m = tid; m < 512; m += 256) {
        int r = m >> 2, w = m & 3;
        smPos [r][w] = g_posbits[(i0 + r) * NWORDS + (j0 >> 5) + w];
        smNeg [r][w] = g_negbits[(i0 + r) * NWORDS + (j0 >> 5) + w];
        smPos2[r][w] = g_posbits[(j0 + r) * NWORDS + (i0 >> 5) + w];
        smNeg2[r][w] = g_negbits[(j0 + r) * NWORDS + (i0 >> 5) + w];
    }

    auto issue_chunk = [&](int kk, int b) {
        const uint32_t bufA = dbase + b * BUFB;
        const uint32_t bufB = bufA + CHUNKF;
        #pragma unroll
        for (int it = 0; it < 4; it++) {
            int g = tid + it * 256;          // 0..1023
            int k = g >> 5, c = g & 31;      // k-row, 16B chunk
            const float* srcA = g_ET + (size_t)(kk + k) * BN + i0 + c * 4;
            const float* srcB = g_ET + (size_t)(kk + k) * BN + j0 + c * 4;
            CP_ASYNC16(bufA + (k * LDA + c * 4) * 4, srcA);
            CP_ASYNC16(bufB + (k * LDA + c * 4) * 4, srcB);
        }
        CP_COMMIT();
    };

    ull acc2[8][4];                 // [row: rb*4+r][pair: cb*2+p]
    #pragma unroll
    for (int r = 0; r < 8; r++)
        #pragma unroll
        for (int c = 0; c < 4; c++) acc2[r][c] = 0ull;

    issue_chunk(0, 0);

    #pragma unroll
    for (int kk = 0; kk < 4; kk++) {
        CP_WAIT0();
        __syncthreads();
        if (kk < 3) issue_chunk((kk + 1) * TK, (kk + 1) & 1);

        const float* As = (const float*)(dsm + (kk & 1) * BUFB);
        const float* Bs = As + CHUNKF / 4;
        #pragma unroll
        for (int k = 0; k < TK; k++) {
            // A: rows ty*4.. and 64+ty*4.. (warp-broadcast)
            float4 a0 = *(const float4*)(As + k * LDA + ty * 4);
            float4 a1 = *(const float4*)(As + k * LDA + 64 + ty * 4);
            // B: cols tx*4.. and 64+tx*4.. -> 256B contiguous/warp, conflict-free
            const ull* bp0 = (const ull*)(Bs + k * LDA + tx * 4);
            const ull* bp1 = (const ull*)(Bs + k * LDA + 64 + tx * 4);
            ull b2[4] = { bp0[0], bp0[1], bp1[0], bp1[1] };
            ull a2[8] = { pack2(a0.x, a0.x), pack2(a0.y, a0.y),
                          pack2(a0.z, a0.z), pack2(a0.w, a0.w),
                          pack2(a1.x, a1.x), pack2(a1.y, a1.y),
                          pack2(a1.z, a1.z), pack2(a1.w, a1.w) };
            #pragma unroll
            for (int r = 0; r < 8; r++)
                #pragma unroll
                for (int c = 0; c < 4; c++)
                    acc2[r][c] = fma2(a2[r], b2[c], acc2[r][c]);
        }
    }

    // unpack accumulators: acc[row8][col8], col index c -> jl = (c>>2)*64 + tx*4 + (c&3)
    float acc[8][8];
    #pragma unroll
    for (int r = 0; r < 8; r++)
        #pragma unroll
        for (int c = 0; c < 4; c++)
            unpack2(acc2[r][c], acc[r][2 * c], acc[r][2 * c + 1]);

    // ---- row-side epilogue -------------------------------------------------
    float cj[8];
    #pragma unroll
    for (int c = 0; c < 8; c++) cj[c] = bCol[(c >> 2) * 64 + tx * 4 + (c & 3)];

    #pragma unroll
    for (int r = 0; r < 8; r++) {
        int li = (r >> 2) * 64 + ty * 4 + (r & 3);
        float base = aRow[li];
        ull bp = 0ull, bn = 0xFFFFFFFFFFFFFFFFull;
        #pragma unroll
        for (int c = 0; c < 8; c++) {
            int jl = (c >> 2) * 64 + tx * 4 + (c & 3);
            float d2 = fmaf(acc[r][c], -2.0f, base + cj[c]);
            unsigned bits = __float_as_uint(fmaxf(d2, 0.0f));
            unsigned j = (unsigned)(j0 + jl);
            unsigned pw = smPos[li][jl >> 5];
            unsigned nw = smNeg[li][jl >> 5];
            if ((pw >> (jl & 31)) & 1u) {
                ull pk = ((ull)bits << 32) | (~j);
                if (pk > bp) bp = pk;               // ties: smaller j wins
            }
            if ((nw >> (jl & 31)) & 1u) {
                ull pk = ((ull)bits << 32) | j;
                if (pk < bn) bn = pk;
            }
        }
        #pragma unroll
        for (int o = 8; o; o >>= 1) {
            ull a = __shfl_down_sync(0xffffffffu, bp, o, 16); if (a > bp) bp = a;
            ull b = __shfl_down_sync(0xffffffffu, bn, o, 16); if (b < bn) bn = b;
        }
        if ((lane & 15) == 0) {
            g_posPart[(size_t)(i0 + li) * PART + bj] = bp;
            g_negPart[(size_t)(i0 + li) * PART + bj] = bn;
        }
    }

    // ---- col-side epilogue (off-diag): rows j over cols i ------------------
    if (!diag) {
        ull (*stP)[16] = (ull (*)[16])dsm;              // reuse buf0
        ull (*stN)[16] = (ull (*)[16])(dsm + 16384);
        float ci[8];
        #pragma unroll
        for (int r = 0; r < 8; r++) ci[r] = aCol[(r >> 2) * 64 + ty * 4 + (r & 3)];

        #pragma unroll
        for (int c = 0; c < 8; c++) {
            int jl = (c >> 2) * 64 + tx * 4 + (c & 3);
            float base = bRow[jl];
            ull bp = 0ull, bn = 0xFFFFFFFFFFFFFFFFull;
            #pragma unroll
            for (int r = 0; r < 8; r++) {
                int il = (r >> 2) * 64 + ty * 4 + (r & 3);
                float d2 = fmaf(acc[r][c], -2.0f, base + ci[r]);
                unsigned bits = __float_as_uint(fmaxf(d2, 0.0f));
                unsigned jx = (unsigned)(i0 + il);      // candidate col = i
                unsigned pw = smPos2[jl][il >> 5];
                unsigned nw = smNeg2[jl][il >> 5];
                if ((pw >> (il & 31)) & 1u) {
                    ull pk = ((ull)bits << 32) | (~jx);
                    if (pk > bp) bp = pk;
                }
                if ((nw >> (il & 31)) & 1u) {
                    ull pk = ((ull)bits << 32) | jx;
                    if (pk < bn) bn = pk;
                }
            }
            stP[jl][ty] = bp;
            stN[jl][ty] = bn;
        }
        __syncthreads();
        int jl = tid & 127;
        if (tid < 128) {
            ull m = 0ull;
            #pragma unroll
            for (int k = 0; k < 16; k++) {
                ull v = stP[jl][(jl + k) & 15]; if (v > m) m = v;
            }
            g_posPart[(size_t)(j0 + jl) * PART + bi] = m;
        } else {
            ull m = 0xFFFFFFFFFFFFFFFFull;
            #pragma unroll
            for (int k = 0; k < 16; k++) {
                ull v = stN[jl][(jl + k) & 15]; if (v < m) m = v;
            }
            g_negPart[(size_t)(j0 + jl) * PART + bi] = m;
        }
    }
}

// ---------------- kernel 3: per-row reduce + exact triplet loss ------------
__global__ void row_kernel(const float* __restrict__ E)
{
    int i = blockIdx.x;
    int t = threadIdx.x;            // 128 threads

    ull bp = 0ull, bn = 0xFFFFFFFFFFFFFFFFull;
    if (t < PART) {
        bp = g_posPart[(size_t)i * PART + t];
        bn = g_negPart[(size_t)i * PART + t];
    }
    #pragma unroll
    for (int o = 16; o; o >>= 1) {
        ull a = __shfl_down_sync(0xffffffffu, bp, o); if (a > bp) bp = a;
        ull b = __shfl_down_sync(0xffffffffu, bn, o); if (b < bn) bn = b;
    }
    __shared__ ull shP, shN;
    if (t == 0) { shP = bp; shN = bn; }
    __syncthreads();
    bp = shP; bn = shN;

    if (bp == 0ull || bn == 0xFFFFFFFFFFFFFFFFull) {   // invalid row
        if (t == 0) { g_loss[i] = 0.0f; g_w[i] = 0.0f; }
        return;
    }
    int pi = (int)(~(unsigned)bp) & (BN - 1);   // undo ~j
    int ni = (int)((unsigned)bn);

    float av = E[(size_t)i  * DD + t];
    float pv = E[(size_t)pi * DD + t];
    float nv = E[(size_t)ni * DD + t];
    float d1 = av - pv + EPSF;
    float d2 = av - nv + EPSF;
    float d3 = pv - nv + EPSF;
    float s1 = d1 * d1, s2 = d2 * d2, s3 = d3 * d3;
    #pragma unroll
    for (int o = 16; o; o >>= 1) {
        s1 += __shfl_down_sync(0xffffffffu, s1, o);
        s2 += __shfl_down_sync(0xffffffffu, s2, o);
        s3 += __shfl_down_sync(0xffffffffu, s3, o);
    }
    __shared__ float r1[4], r2[4], r3[4];
    if ((t & 31) == 0) { r1[t >> 5] = s1; r2[t >> 5] = s2; r3[t >> 5] = s3; }
    __syncthreads();
    if (t == 0) {
        float S1 = r1[0] + r1[1] + r1[2] + r1[3];
        float S2 = r2[0] + r2[1] + r2[2] + r2[3];
        float S3 = r3[0] + r3[1] + r3[2] + r3[3];
        float ap = sqrtf(S1), an = sqrtf(S2), pn = sqrtf(S3);
        float loss = fmaxf(ap - fminf(an, pn) + 1.0f, 0.0f);
        g_loss[i] = loss;
        g_w[i] = 1.0f;
    }
}

// ---------------- kernel 4: deterministic scalar reduction -----------------
__global__ void final_kernel(float* __restrict__ out)
{
    int t = threadIdx.x;            // 1024 threads
    float ls = 0.0f, ws = 0.0f;
    for (int r = t; r < BN; r += 1024) { ls += g_loss[r]; ws += g_w[r]; }
    #pragma unroll
    for (int o = 16; o; o >>= 1) {
        ls += __shfl_down_sync(0xffffffffu, ls, o);
        ws += __shfl_down_sync(0xffffffffu, ws, o);
    }
    __shared__ float sl[32], sw[32];
    if ((t & 31) == 0) { sl[t >> 5] = ls; sw[t >> 5] = ws; }
    __syncthreads();
    if (t == 0) {
        float L = 0.0f, W = 0.0f;
        for (int w = 0; w < 32; w++) { L += sl[w]; W += sw[w]; }
        out[0] = L / fmaxf(W, 1.0f);
    }
}

// ---------------- launch ----------------------------------------------------
extern "C" void kernel_launch(void* const* d_in, const int* in_sizes, int n_in,
                              void* d_out, int out_size)
{
    const float*    E   = (const float*)d_in[0];
    const int*      tgt = (const int*)d_in[1];
    const unsigned* P   = (const unsigned*)d_in[2];
    const unsigned* N   = (const unsigned*)d_in[3];
    float* out = (float*)d_out;

    static int configured = 0;
    if (!configured) {
        cudaFuncSetAttribute(main_kernel,
                             cudaFuncAttributeMaxDynamicSharedMemorySize, DSMEM);
        configured = 1;
    }

    {
        dim3 tg(BN / 32, DD / 32);
        transpose_kernel<<<tg, 256>>>(E);
    }
    mask_kernel<<<BN / RPB, 256>>>(E, tgt, P, N);
    main_kernel<<<NBLK, 256, DSMEM>>>();
    row_kernel<<<BN, 128>>>(E);
    final_kernel<<<1, 1024>>>(out);
}